// round 15
// baseline (speedup 1.0000x reference)
#include <cuda_runtime.h>
#include <cuda_fp16.h>
#include <math.h>

#define BB   4
#define LL   16384
#define SCALE 0.08838834764831845f   // 128^-0.5

typedef unsigned long long ull;
typedef ulonglong2 ull2;

__device__ __forceinline__ ull pk2(float a, float b) {
    ull r; asm("mov.b64 %0,{%1,%2};" : "=l"(r) : "f"(a), "f"(b)); return r;
}
__device__ __forceinline__ ull dup2(float a) { return pk2(a, a); }
__device__ __forceinline__ void up2(ull v, float& a, float& b) {
    asm("mov.b64 {%0,%1},%2;" : "=f"(a), "=f"(b) : "l"(v));
}
__device__ __forceinline__ ull fma2(ull a, ull b, ull c) {
    ull d; asm("fma.rn.f32x2 %0,%1,%2,%3;" : "=l"(d) : "l"(a), "l"(b), "l"(c)); return d;
}
__device__ __forceinline__ ull mul2(ull a, ull b) {
    ull d; asm("mul.rn.f32x2 %0,%1,%2;" : "=l"(d) : "l"(a), "l"(b)); return d;
}
__device__ __forceinline__ float hadd2(ull v) { float a, b; up2(v, a, b); return a + b; }

// ---------------- scratch ----------------------------------------------------
__device__ __align__(16) float  g_winv[BB*256*64*64];   // (b,r,t,c) window V
__device__ __align__(16) float  g_vtok[BB*256*64*64];   // (b,r,t,c) bra V token-major
__device__ __align__(16) float  g_qb  [BB*8*256*64*8];  // (b,h,r,t,d) PRE-SCALED
__device__ __align__(16) __half g_kh  [BB*8*256*64*8];  // (b,h,r,t,d) fp16 k
__device__ __align__(16) __half g_vh  [BB*8*256*64*8];  // (b,h,r,t,d) fp16 v
__device__ __align__(16) float  g_qr  [BB*256*64];
__device__ __align__(16) float  g_krT [BB*64*256];      // channel-major pooled k
__device__ int   g_idx [BB*256*4];
__device__ __align__(16) float g_mid [(size_t)BB*LL*128];   // attention outputs
__device__ __align__(16) float g_lepe[(size_t)BB*LL*128];   // lepe (added in kF1)
__device__ __align__(16) float g_cq  [(size_t)BB*LL*128];   // token-major
__device__ __align__(16) float g_ck  [(size_t)BB*LL*128];
__device__ __align__(16) float g_cv  [(size_t)BB*LL*128];
__device__ float g_norm2[2*BB*128];
__device__ float g_gram[32*256];
__device__ float g_attn[32*256];

// ---------------- kA: window QKV GEMM + window attention --------------------
__global__ void kA_win(const float* __restrict__ x, const float* __restrict__ w,
                       const float* __restrict__ bias) {
    extern __shared__ float sm[];
    float* s_xT  = sm;            // 64 k x 68 m
    float* s_w   = sm + 64*68;    // 64 x 192 (reused as s_qkv)
    float* s_qkv = s_w;
    int wid = blockIdx.x;
    int b = wid >> 8, r = wid & 255, ry = r >> 4, rx = r & 15;
    int tid = threadIdx.x;

    for (int i = tid; i < 4096; i += 256) {
        int t = i >> 6, c = i & 63;
        int y = ry*8 + (t >> 3), xx = rx*8 + (t & 7);
        s_xT[c*68 + t] = x[(((size_t)b*128 + y)*128 + xx)*128 + c];
    }
    for (int i = tid; i < 12288; i += 256) s_w[i] = w[i];
    __syncthreads();

    int t_m = tid & 15, t_n = tid >> 4;     // m = t_m*4, n = t_n*12
    ull acc[4][6];
    #pragma unroll
    for (int i = 0; i < 4; i++)
        #pragma unroll
        for (int j = 0; j < 6; j++) acc[i][j] = 0ull;
    for (int k = 0; k < 64; k++) {
        float4 a4 = *(const float4*)(s_xT + k*68 + t_m*4);
        ull a0 = dup2(a4.x), a1 = dup2(a4.y), a2 = dup2(a4.z), a3 = dup2(a4.w);
        const ull2* bp = (const ull2*)(s_w + k*192 + t_n*12);
        ull2 B0 = bp[0], B1 = bp[1], B2 = bp[2];
        ull b0=B0.x, b1=B0.y, b2=B1.x, b3=B1.y, b4=B2.x, b5=B2.y;
        acc[0][0]=fma2(a0,b0,acc[0][0]); acc[0][1]=fma2(a0,b1,acc[0][1]);
        acc[0][2]=fma2(a0,b2,acc[0][2]); acc[0][3]=fma2(a0,b3,acc[0][3]);
        acc[0][4]=fma2(a0,b4,acc[0][4]); acc[0][5]=fma2(a0,b5,acc[0][5]);
        acc[1][0]=fma2(a1,b0,acc[1][0]); acc[1][1]=fma2(a1,b1,acc[1][1]);
        acc[1][2]=fma2(a1,b2,acc[1][2]); acc[1][3]=fma2(a1,b3,acc[1][3]);
        acc[1][4]=fma2(a1,b4,acc[1][4]); acc[1][5]=fma2(a1,b5,acc[1][5]);
        acc[2][0]=fma2(a2,b0,acc[2][0]); acc[2][1]=fma2(a2,b1,acc[2][1]);
        acc[2][2]=fma2(a2,b2,acc[2][2]); acc[2][3]=fma2(a2,b3,acc[2][3]);
        acc[2][4]=fma2(a2,b4,acc[2][4]); acc[2][5]=fma2(a2,b5,acc[2][5]);
        acc[3][0]=fma2(a3,b0,acc[3][0]); acc[3][1]=fma2(a3,b1,acc[3][1]);
        acc[3][2]=fma2(a3,b2,acc[3][2]); acc[3][3]=fma2(a3,b3,acc[3][3]);
        acc[3][4]=fma2(a3,b4,acc[3][4]); acc[3][5]=fma2(a3,b5,acc[3][5]);
    }
    __syncthreads();
    {
        float bb[12];
        #pragma unroll
        for (int j = 0; j < 12; j++) bb[j] = __ldg(bias + t_n*12 + j);
        #pragma unroll
        for (int i = 0; i < 4; i++)
            #pragma unroll
            for (int j = 0; j < 6; j++) {
                float lo, hi; up2(acc[i][j], lo, hi);
                s_qkv[(t_m*4+i)*192 + t_n*12 + 2*j]     = lo + bb[2*j];
                s_qkv[(t_m*4+i)*192 + t_n*12 + 2*j + 1] = hi + bb[2*j+1];
            }
    }
    __syncthreads();

    size_t base = (size_t)wid * 4096;
    for (int i = tid; i < 4096; i += 256) {
        int t = i >> 6, c = i & 63;
        g_winv[base + i] = s_qkv[t*192 + 128 + c];
    }

    // attention: warp = head, 2 q-rows per thread
    int h = tid >> 5, lane = tid & 31;
    ull sc = dup2(SCALE);
    const ull2* qp0 = (const ull2*)(s_qkv + lane*192 + h*8);
    const ull2* qp1 = (const ull2*)(s_qkv + (lane+32)*192 + h*8);
    ull2 Q0a = qp0[0], Q0b = qp0[1], Q1a = qp1[0], Q1b = qp1[1];
    ull q0[4] = {mul2(Q0a.x,sc), mul2(Q0a.y,sc), mul2(Q0b.x,sc), mul2(Q0b.y,sc)};
    ull q1[4] = {mul2(Q1a.x,sc), mul2(Q1a.y,sc), mul2(Q1b.x,sc), mul2(Q1b.y,sc)};
    float ssum0 = 0.f, ssum1 = 0.f;
    ull a0[4] = {0,0,0,0}, a1[4] = {0,0,0,0};
    #pragma unroll 2
    for (int j = 0; j < 64; j++) {
        const ull2* kp = (const ull2*)(s_qkv + j*192 + 64 + h*8);
        ull2 K0 = kp[0], K1 = kp[1];
        ull s20 = fma2(q0[0],K0.x, fma2(q0[1],K0.y, fma2(q0[2],K1.x, mul2(q0[3],K1.y))));
        ull s21 = fma2(q1[0],K0.x, fma2(q1[1],K0.y, fma2(q1[2],K1.x, mul2(q1[3],K1.y))));
        float e0 = __expf(hadd2(s20));
        float e1 = __expf(hadd2(s21));
        ssum0 += e0; ssum1 += e1;
        ull e0d = dup2(e0), e1d = dup2(e1);
        const ull2* vp = (const ull2*)(s_qkv + j*192 + 128 + h*8);
        ull2 V0 = vp[0], V1 = vp[1];
        a0[0]=fma2(e0d,V0.x,a0[0]); a0[1]=fma2(e0d,V0.y,a0[1]);
        a0[2]=fma2(e0d,V1.x,a0[2]); a0[3]=fma2(e0d,V1.y,a0[3]);
        a1[0]=fma2(e1d,V0.x,a1[0]); a1[1]=fma2(e1d,V0.y,a1[1]);
        a1[2]=fma2(e1d,V1.x,a1[2]); a1[3]=fma2(e1d,V1.y,a1[3]);
    }
    ull i0 = dup2(1.f/ssum0), i1 = dup2(1.f/ssum1);
    {
        int row = lane;
        int y = ry*8 + (row>>3), xx = rx*8 + (row&7);
        ull* mo = (ull*)(g_mid + ((size_t)b*LL + y*128 + xx)*128 + h*8);
        mo[0]=mul2(a0[0],i0); mo[1]=mul2(a0[1],i0); mo[2]=mul2(a0[2],i0); mo[3]=mul2(a0[3],i0);
        row = lane + 32;
        y = ry*8 + (row>>3); xx = rx*8 + (row&7);
        mo = (ull*)(g_mid + ((size_t)b*LL + y*128 + xx)*128 + h*8);
        mo[0]=mul2(a1[0],i1); mo[1]=mul2(a1[1],i1); mo[2]=mul2(a1[2],i1); mo[3]=mul2(a1[3],i1);
    }
}

// ---------------- kB: BRA QKV GEMM (head-major q/kh/vh + token-major V) -----
__global__ void kB_bra(const float* __restrict__ x, const float* __restrict__ w,
                       const float* __restrict__ bias) {
    extern __shared__ float sm[];
    float* s_xT  = sm;
    float* s_w   = sm + 64*68;
    float* s_qkv = s_w;
    int wid = blockIdx.x;
    int b = wid >> 8, r = wid & 255, ry = r >> 4, rx = r & 15;
    int tid = threadIdx.x;

    for (int i = tid; i < 4096; i += 256) {
        int t = i >> 6, c = i & 63;
        int y = ry*8 + (t >> 3), xx = rx*8 + (t & 7);
        s_xT[c*68 + t] = x[(((size_t)b*128 + y)*128 + xx)*128 + 64 + c];
    }
    for (int i = tid; i < 12288; i += 256) s_w[i] = w[i];
    __syncthreads();

    int t_m = tid & 15, t_n = tid >> 4;
    ull acc[4][6];
    #pragma unroll
    for (int i = 0; i < 4; i++)
        #pragma unroll
        for (int j = 0; j < 6; j++) acc[i][j] = 0ull;
    for (int k = 0; k < 64; k++) {
        float4 a4 = *(const float4*)(s_xT + k*68 + t_m*4);
        ull a0 = dup2(a4.x), a1 = dup2(a4.y), a2 = dup2(a4.z), a3 = dup2(a4.w);
        const ull2* bp = (const ull2*)(s_w + k*192 + t_n*12);
        ull2 B0 = bp[0], B1 = bp[1], B2 = bp[2];
        ull b0=B0.x, b1=B0.y, b2=B1.x, b3=B1.y, b4=B2.x, b5=B2.y;
        acc[0][0]=fma2(a0,b0,acc[0][0]); acc[0][1]=fma2(a0,b1,acc[0][1]);
        acc[0][2]=fma2(a0,b2,acc[0][2]); acc[0][3]=fma2(a0,b3,acc[0][3]);
        acc[0][4]=fma2(a0,b4,acc[0][4]); acc[0][5]=fma2(a0,b5,acc[0][5]);
        acc[1][0]=fma2(a1,b0,acc[1][0]); acc[1][1]=fma2(a1,b1,acc[1][1]);
        acc[1][2]=fma2(a1,b2,acc[1][2]); acc[1][3]=fma2(a1,b3,acc[1][3]);
        acc[1][4]=fma2(a1,b4,acc[1][4]); acc[1][5]=fma2(a1,b5,acc[1][5]);
        acc[2][0]=fma2(a2,b0,acc[2][0]); acc[2][1]=fma2(a2,b1,acc[2][1]);
        acc[2][2]=fma2(a2,b2,acc[2][2]); acc[2][3]=fma2(a2,b3,acc[2][3]);
        acc[2][4]=fma2(a2,b4,acc[2][4]); acc[2][5]=fma2(a2,b5,acc[2][5]);
        acc[3][0]=fma2(a3,b0,acc[3][0]); acc[3][1]=fma2(a3,b1,acc[3][1]);
        acc[3][2]=fma2(a3,b2,acc[3][2]); acc[3][3]=fma2(a3,b3,acc[3][3]);
        acc[3][4]=fma2(a3,b4,acc[3][4]); acc[3][5]=fma2(a3,b5,acc[3][5]);
    }
    __syncthreads();
    {
        float bb[12];
        #pragma unroll
        for (int j = 0; j < 12; j++) bb[j] = __ldg(bias + t_n*12 + j);
        #pragma unroll
        for (int i = 0; i < 4; i++)
            #pragma unroll
            for (int j = 0; j < 6; j++) {
                float lo, hi; up2(acc[i][j], lo, hi);
                s_qkv[(t_m*4+i)*192 + t_n*12 + 2*j]     = lo + bb[2*j];
                s_qkv[(t_m*4+i)*192 + t_n*12 + 2*j + 1] = hi + bb[2*j+1];
            }
    }
    __syncthreads();

    for (int i = tid; i < 4096; i += 256) {
        int hh = i >> 9, rest = i & 511;
        int t = rest >> 3, d = rest & 7;
        size_t off = ((size_t)(b*8 + hh)*256 + r)*512 + rest;
        g_qb[off] = s_qkv[t*192 + hh*8 + d] * SCALE;            // pre-scaled
        g_kh[off] = __float2half(s_qkv[t*192 + 64 + hh*8 + d]); // fp16 k
        g_vh[off] = __float2half(s_qkv[t*192 + 128 + hh*8 + d]);// fp16 v
    }
    size_t base = (size_t)wid * 4096;
    for (int i = tid; i < 4096; i += 256) {
        int t = i >> 6, c = i & 63;
        g_vtok[base + i] = s_qkv[t*192 + 128 + c];
    }
    if (tid < 64) {
        float sq = 0.f, sk = 0.f;
        for (int t = 0; t < 64; t++) {
            sq += s_qkv[t*192 + tid];
            sk += s_qkv[t*192 + 64 + tid];
        }
        g_qr[wid*64 + tid] = sq * 0.015625f;
        g_krT[((size_t)b*64 + tid)*256 + r] = sk * 0.015625f;
    }
}

// ---------------- kC: routing (coalesced) + warp-register top-4 + zeroing ---
__global__ void kC_route() {
    __shared__ float s_q[64];
    __shared__ float s_a[256];
    int bx = blockIdx.x;
    int b = bx >> 8, i = bx & 255;
    int tid = threadIdx.x;
    if (bx < 32) g_gram[bx*256 + tid] = 0.f;
    else if (bx < 36) g_norm2[(bx-32)*256 + tid] = 0.f;
    if (tid < 64) s_q[tid] = g_qr[(b*256 + i)*64 + tid];
    __syncthreads();
    const float* krT = g_krT + (size_t)b*64*256 + tid;   // lane-coalesced
    float a = 0.f;
    #pragma unroll 8
    for (int c = 0; c < 64; c++) a += s_q[c]*krT[c*256];
    s_a[tid] = a;
    __syncthreads();
    if (tid < 32) {
        float v[8];
        #pragma unroll
        for (int j = 0; j < 8; j++) v[j] = s_a[tid + j*32];
        #pragma unroll
        for (int s = 0; s < 4; s++) {
            float bv = v[0]; int bj = 0;
            #pragma unroll
            for (int j = 1; j < 8; j++)
                if (v[j] > bv) { bv = v[j]; bj = j; }
            int bidx = tid + bj*32;
            #pragma unroll
            for (int off = 16; off > 0; off >>= 1) {
                float ov = __shfl_down_sync(0xffffffffu, bv, off);
                int   oi = __shfl_down_sync(0xffffffffu, bidx, off);
                if (ov > bv || (ov == bv && oi < bidx)) { bv = ov; bidx = oi; }
            }
            bidx = __shfl_sync(0xffffffffu, bidx, 0);
            if (tid == 0) g_idx[(b*256 + i)*4 + s] = bidx;
            if ((bidx & 31) == tid) v[bidx >> 5] = -INFINITY;
        }
    }
}

// ---------------- kD: BRA attn (4 heads/block, fp16 k+v, 2 q/thread) --------
__global__ void kD_attn() {
    extern __shared__ char smd[];
    __half* s_k = (__half*)smd;              // 4*256*8 halfs = 16KB
    __half* s_v = (__half*)(smd + 16384);    // 16KB
    __shared__ int s_i4[4];
    int bid = blockIdx.x;                    // 2048: b(4) x hp(2) x r(256)
    int b = bid >> 9, hp = (bid >> 8) & 1, r = bid & 255;
    int tid = threadIdx.x;                   // 128
    if (tid < 4) s_i4[tid] = g_idx[(b*256 + r)*4 + tid];
    __syncthreads();
    for (int i = tid; i < 1024; i += 128) {  // k+v: 16B per key each
        int hl = i >> 8, key = i & 255;
        int reg = s_i4[key >> 6], t = key & 63;
        size_t off = ((size_t)(b*8 + hp*4 + hl)*256 + reg)*512 + t*8;
        *(uint4*)(s_k + (size_t)i*8) = *(const uint4*)(g_kh + off);
        *(uint4*)(s_v + (size_t)i*8) = *(const uint4*)(g_vh + off);
    }
    __syncthreads();
    int hl = tid >> 5, lane = tid & 31;      // warp = head; rows lane, lane+32
    int h = hp*4 + hl;
    size_t qbase = ((size_t)(b*8 + h)*256 + r)*512;
    const float2* qa = (const float2*)(g_qb + qbase + lane*8);       // pre-scaled
    const float2* qb2 = (const float2*)(g_qb + qbase + (lane+32)*8);
    __half2 qh0[4], qh1[4];
    #pragma unroll
    for (int d = 0; d < 4; d++) {
        qh0[d] = __float22half2_rn(qa[d]);
        qh1[d] = __float22half2_rn(qb2[d]);
    }
    const uint4* kp = (const uint4*)(s_k + (size_t)hl*2048);
    const uint4* vp = (const uint4*)(s_v + (size_t)hl*2048);
    float ss0 = 0.f, ss1 = 0.f;
    ull a00=0,a01=0,a02=0,a03=0, a10=0,a11=0,a12=0,a13=0;
    #pragma unroll 4
    for (int j = 0; j < 256; j++) {
        uint4 kk = kp[j];
        __half2 k0 = *(__half2*)&kk.x, k1 = *(__half2*)&kk.y,
                k2 = *(__half2*)&kk.z, k3 = *(__half2*)&kk.w;
        __half2 h0 = __hfma2(qh0[1], k1, __hmul2(qh0[0], k0));
        h0 = __hfma2(qh0[3], k3, __hfma2(qh0[2], k2, h0));
        __half2 h1 = __hfma2(qh1[1], k1, __hmul2(qh1[0], k0));
        h1 = __hfma2(qh1[3], k3, __hfma2(qh1[2], k2, h1));
        float2 f0 = __half22float2(h0);
        float2 f1 = __half22float2(h1);
        float e0 = __expf(f0.x + f0.y);
        float e1 = __expf(f1.x + f1.y);
        ss0 += e0; ss1 += e1;
        ull e0d = dup2(e0), e1d = dup2(e1);
        uint4 vv = vp[j];
        float2 v0 = __half22float2(*(const __half2*)&vv.x);
        float2 v1 = __half22float2(*(const __half2*)&vv.y);
        float2 v2 = __half22float2(*(const __half2*)&vv.z);
        float2 v3 = __half22float2(*(const __half2*)&vv.w);
        ull V0 = pk2(v0.x, v0.y), V1 = pk2(v1.x, v1.y);
        ull V2 = pk2(v2.x, v2.y), V3 = pk2(v3.x, v3.y);
        a00 = fma2(e0d, V0, a00); a01 = fma2(e0d, V1, a01);
        a02 = fma2(e0d, V2, a02); a03 = fma2(e0d, V3, a03);
        a10 = fma2(e1d, V0, a10); a11 = fma2(e1d, V1, a11);
        a12 = fma2(e1d, V2, a12); a13 = fma2(e1d, V3, a13);
    }
    ull i0 = dup2(1.f/ss0), i1 = dup2(1.f/ss1);
    {
        int row = lane;
        int y = (r >> 4)*8 + (row >> 3), xx = (r & 15)*8 + (row & 7);
        ull* mo = (ull*)(g_mid + ((size_t)b*LL + y*128 + xx)*128 + 64 + h*8);
        mo[0]=mul2(a00,i0); mo[1]=mul2(a01,i0); mo[2]=mul2(a02,i0); mo[3]=mul2(a03,i0);
        row = lane + 32;
        y = (r >> 4)*8 + (row >> 3); xx = (r & 15)*8 + (row & 7);
        mo = (ull*)(g_mid + ((size_t)b*LL + y*128 + xx)*128 + 64 + h*8);
        mo[0]=mul2(a10,i1); mo[1]=mul2(a11,i1); mo[2]=mul2(a12,i1); mo[3]=mul2(a13,i1);
    }
}

// ---------------- kE: depthwise 3x3 LEPE, smem-tiled (writes g_lepe) --------
__global__ void kE_lepe(const float* __restrict__ lw, const float* __restrict__ lb) {
    extern __shared__ float se[];
    float* s_v  = se;             // vtok patch: 100 pos x 64 ch = 6400
    float* s_wi = se + 6400;      // winv patch: 6400
    float* s_lw = se + 12800;     // 128*9 = 1152
    float* s_lb = se + 13952;     // 128
    int bid = blockIdx.x;         // 1024 = b(4) x r(256)
    int b = bid >> 8, r = bid & 255, ry = r >> 4, rx = r & 15;
    int tid = threadIdx.x;        // 256

    for (int i = tid; i < 1152; i += 256) s_lw[i] = lw[i];
    if (tid < 128) s_lb[tid] = lb[tid];
    for (int i = tid; i < 3200; i += 256) {   // 2 arrays x 100 pos x 16 float4
        int half = i >= 1600;
        int rem = half ? i - 1600 : i;
        int pos = rem >> 4, f4 = rem & 15;
        int py = pos / 10, px = pos - py*10;
        int y = ry*8 - 1 + py, x = rx*8 - 1 + px;
        float4 val = make_float4(0.f, 0.f, 0.f, 0.f);
        if (y >= 0 && y < 128 && x >= 0 && x < 128) {
            int rr = (y >> 3)*16 + (x >> 3), tt = (y & 7)*8 + (x & 7);
            const float* src = half ? g_winv : g_vtok;
            val = *(const float4*)(src + ((size_t)(b*256 + rr))*4096 + tt*64 + f4*4);
        }
        float* dst = half ? s_wi : s_v;
        *(float4*)(dst + pos*64 + f4*4) = val;
    }
    __syncthreads();

    for (int i = tid; i < 8192; i += 256) {   // 64 tokens x 128 ch
        int tok = i >> 7, c = i & 127;
        int iy = tok >> 3, ix = tok & 7;
        const float* s_src = (c < 64) ? s_v : s_wi;
        int cc = c & 63;
        float acc = s_lb[c];
        const float* wr = s_lw + c*9;
        #pragma unroll
        for (int ky = 0; ky < 3; ky++)
            #pragma unroll
            for (int kx = 0; kx < 3; kx++)
                acc += s_src[((iy+ky)*10 + (ix+kx))*64 + cc] * wr[ky*3 + kx];
        int y = ry*8 + iy, x = rx*8 + ix;
        g_lepe[((size_t)b*LL + y*128 + x)*128 + c] = acc;
    }
}

// ---------------- kF1: CA-qkv GEMM, A = g_mid + g_lepe, single launch -------
__global__ void kF1_caqkv(const float* __restrict__ w, const float* __restrict__ bias) {
    extern __shared__ float sm[];
    float* AsT = sm;          // [128 k][68 m]
    float* Bs  = sm + 8704;   // [128 k][128 n] (reused as Cs)
    float* Cs  = Bs;
    int m0 = blockIdx.x * 64;
    int tid = threadIdx.x;

    for (int i = tid; i < 8192; i += 256) {
        int t = i >> 7, k = i & 127;
        size_t go = (size_t)(m0 + t)*128 + k;
        AsT[k*68 + t] = g_mid[go] + g_lepe[go];
    }

    int t_m = tid & 15, t_n = tid >> 4;
    for (int nb = 0; nb < 3; nb++) {
        __syncthreads();
        for (int i = tid; i < 16384; i += 256) {
            int k = i >> 7, n = i & 127;
            Bs[i] = w[k*384 + nb*128 + n];
        }
        __syncthreads();

        ull acc[4][4];
        #pragma unroll
        for (int i = 0; i < 4; i++)
            #pragma unroll
            for (int j = 0; j < 4; j++) acc[i][j] = 0ull;
        #pragma unroll 4
        for (int k = 0; k < 128; k++) {
            float4 a4 = *(const float4*)(AsT + k*68 + t_m*4);
            ull a0 = dup2(a4.x), a1 = dup2(a4.y), a2 = dup2(a4.z), a3 = dup2(a4.w);
            const ull2* bp = (const ull2*)(Bs + k*128 + t_n*8);
            ull2 B0 = bp[0], B1 = bp[1];
            ull b0=B0.x, b1=B0.y, b2=B1.x, b3=B1.y;
            acc[0][0]=fma2(a0,b0,acc[0][0]); acc[0][1]=fma2(a0,b1,acc[0][1]);
            acc[0][2]=fma2(a0,b2,acc[0][2]); acc[0][3]=fma2(a0,b3,acc[0][3]);
            acc[1][0]=fma2(a1,b0,acc[1][0]); acc[1][1]=fma2(a1,b1,acc[1][1]);
            acc[1][2]=fma2(a1,b2,acc[1][2]); acc[1][3]=fma2(a1,b3,acc[1][3]);
            acc[2][0]=fma2(a2,b0,acc[2][0]); acc[2][1]=fma2(a2,b1,acc[2][1]);
            acc[2][2]=fma2(a2,b2,acc[2][2]); acc[2][3]=fma2(a2,b3,acc[2][3]);
            acc[3][0]=fma2(a3,b0,acc[3][0]); acc[3][1]=fma2(a3,b1,acc[3][1]);
            acc[3][2]=fma2(a3,b2,acc[3][2]); acc[3][3]=fma2(a3,b3,acc[3][3]);
        }
        __syncthreads();

        {
            float bb[8];
            #pragma unroll
            for (int j = 0; j < 8; j++) bb[j] = __ldg(bias + nb*128 + t_n*8 + j);
            #pragma unroll
            for (int i = 0; i < 4; i++)
                #pragma unroll
                for (int j = 0; j < 4; j++) {
                    float lo, hi; up2(acc[i][j], lo, hi);
                    Cs[(t_m*4+i)*132 + t_n*8 + 2*j]     = lo + bb[2*j];
                    Cs[(t_m*4+i)*132 + t_n*8 + 2*j + 1] = hi + bb[2*j+1];
                }
        }
        __syncthreads();
        float* dst = (nb == 0) ? g_cq : (nb == 1) ? g_ck : g_cv;
        for (int i = tid; i < 2048; i += 256) {
            int m = i >> 5, nf = i & 31;
            *(float4*)(dst + (size_t)(m0 + m)*128 + nf*4) = *(const float4*)(Cs + m*132 + nf*4);
        }
    }
}

// ---------------- kF23: norms + grams, channel-major tiles (pad 66) ---------
__global__ void kF23() {
    extern __shared__ float sm[];
    float* qs = sm;            // 128 ch x 66 t
    float* ks = sm + 8448;
    int bid = blockIdx.x;      // 1024 = b(4) x chunk(256)
    int b = bid >> 8, ch = bid & 255;
    int l0 = ch*64;
    int tid = threadIdx.x;
    const float4* qsrc = (const float4*)(g_cq + ((size_t)b*LL + l0)*128);
    const float4* ksrc = (const float4*)(g_ck + ((size_t)b*LL + l0)*128);
    for (int i = tid; i < 2048; i += 256) {
        int t = i >> 5, nf = i & 31;
        float4 q4 = qsrc[t*32 + nf];
        float4 k4 = ksrc[t*32 + nf];
        int c = nf*4;
        qs[(c+0)*66 + t] = q4.x; qs[(c+1)*66 + t] = q4.y;
        qs[(c+2)*66 + t] = q4.z; qs[(c+3)*66 + t] = q4.w;
        ks[(c+0)*66 + t] = k4.x; ks[(c+1)*66 + t] = k4.y;
        ks[(c+2)*66 + t] = k4.z; ks[(c+3)*66 + t] = k4.w;
    }
    __syncthreads();
    {
        const ull* bp = (tid < 128) ? (const ull*)(qs + tid*66)
                                    : (const ull*)(ks + (tid - 128)*66);
        ull acc2 = 0ull;
        #pragma unroll 8
        for (int t2 = 0; t2 < 32; t2++) { ull v = bp[t2]; acc2 = fma2(v, v, acc2); }
        atomicAdd(&g_norm2[((tid < 128) ? 0 : 512) + b*128 + (tid & 127)], hadd2(acc2));
    }
    int d = tid >> 4, e = tid & 15;
    #pragma unroll
    for (int h = 0; h < 8; h++) {
        const ull* qp2 = (const ull*)(qs + (h*16 + d)*66);
        const ull* kp2 = (const ull*)(ks + (h*16 + e)*66);
        ull acc2 = 0ull;
        #pragma unroll 8
        for (int t2 = 0; t2 < 32; t2++) acc2 = fma2(qp2[t2], kp2[t2], acc2);
        atomicAdd(&g_gram[(b*8 + h)*256 + tid], hadd2(acc2));
    }
}

// ---------------- kF3b: normalize + softmax ----------------------------------
__global__ void kF3b(const float* __restrict__ temp) {
    __shared__ float smm[256];
    int bh = blockIdx.x;
    int b = bh >> 3, h = bh & 7;
    int tid = threadIdx.x;
    int d = tid >> 4, e = tid & 15;
    int rowq = b*128 + h*16;
    float nq = fmaxf(sqrtf(g_norm2[rowq + d]), 1e-12f);
    float nk = fmaxf(sqrtf(g_norm2[512 + rowq + e]), 1e-12f);
    smm[tid] = g_gram[bh*256 + tid] / (nq*nk) * __ldg(temp + h);
    __syncthreads();
    if (tid < 16) {
        float mx = -INFINITY;
        for (int j = 0; j < 16; j++) mx = fmaxf(mx, smm[tid*16 + j]);
        float ssum = 0.f, ex[16];
        for (int j = 0; j < 16; j++) { ex[j] = __expf(smm[tid*16 + j] - mx); ssum += ex[j]; }
        float inv = 1.f/ssum;
        for (int j = 0; j < 16; j++) g_attn[bh*256 + tid*16 + j] = ex[j]*inv;
    }
}

// ---------------- kF4: cout mix (attn pad 18) + 128x128 projection ----------
__global__ void kF4_out(const float* __restrict__ pw, const float* __restrict__ pb,
                        float* __restrict__ out) {
    extern __shared__ float sm[];
    float* s_attn = sm;           // 128 ch x 18
    float* s_cv   = sm + 2304;    // 64 x 128
    float* coutT  = sm + 10496;   // 128 k x 68 m
    int tok0 = blockIdx.x * 64;
    int b = tok0 >> 14;
    int tid = threadIdx.x;
    for (int i = tid; i < 2048; i += 256)
        s_attn[(i >> 4)*18 + (i & 15)] = g_attn[b*2048 + i];
    for (int i = tid; i < 8192; i += 256) s_cv[i] = g_cv[(size_t)tok0*128 + i];
    __syncthreads();
    for (int i = tid; i < 8192; i += 256) {
        int m = i >> 7, chn = i & 127;
        int h = chn >> 4;
        const ull* ap  = (const ull*)(s_attn + chn*18);
        const ull2* cvp = (const ull2*)(s_cv + m*128 + h*16);
        ull2 C0 = cvp[0], C1 = cvp[1], C2 = cvp[2], C3 = cvp[3];
        ull acc = mul2(ap[0], C0.x);
        acc = fma2(ap[1], C0.y, acc);
        acc = fma2(ap[2], C1.x, acc);
        acc = fma2(ap[3], C1.y, acc);
        acc = fma2(ap[4], C2.x, acc);
        acc = fma2(ap[5], C2.y, acc);
        acc = fma2(ap[6], C3.x, acc);
        acc = fma2(ap[7], C3.y, acc);
        coutT[chn*68 + m] = hadd2(acc);
    }
    __syncthreads();
    int t_m = tid & 15, t_n = tid >> 4;
    ull acc[4][4];
    #pragma unroll
    for (int i = 0; i < 4; i++)
        #pragma unroll
        for (int j = 0; j < 4; j++) acc[i][j] = 0ull;
    #pragma unroll 4
    for (int k = 0; k < 128; k++) {
        float4 a4 = *(const float4*)(coutT + k*68 + t_m*4);
        ull a0 = dup2(a4.x), a1 = dup2(a4.y), a2 = dup2(a4.z), a3 = dup2(a4.w);
        float4 w0 = __ldg((const float4*)(pw + k*128 + t_n*8));
        float4 w1 = __ldg((const float4*)(pw + k*128 + t_n*8 + 4));
        ull b0 = pk2(w0.x, w0.y), b1 = pk2(w0.z, w0.w);
        ull b2 = pk2(w1.x, w1.y), b3 = pk2(w1.z, w1.w);
        acc[0][0]=fma2(a0,b0,acc[0][0]); acc[0][1]=fma2(a0,b1,acc[0][1]);
        acc[0][2]=fma2(a0,b2,acc[0][2]); acc[0][3]=fma2(a0,b3,acc[0][3]);
        acc[1][0]=fma2(a1,b0,acc[1][0]); acc[1][1]=fma2(a1,b1,acc[1][1]);
        acc[1][2]=fma2(a1,b2,acc[1][2]); acc[1][3]=fma2(a1,b3,acc[1][3]);
        acc[2][0]=fma2(a2,b0,acc[2][0]); acc[2][1]=fma2(a2,b1,acc[2][1]);
        acc[2][2]=fma2(a2,b2,acc[2][2]); acc[2][3]=fma2(a2,b3,acc[2][3]);
        acc[3][0]=fma2(a3,b0,acc[3][0]); acc[3][1]=fma2(a3,b1,acc[3][1]);
        acc[3][2]=fma2(a3,b2,acc[3][2]); acc[3][3]=fma2(a3,b3,acc[3][3]);
    }
    float4 pb0 = __ldg((const float4*)(pb + t_n*8));
    float4 pb1 = __ldg((const float4*)(pb + t_n*8 + 4));
    float bb[8] = {pb0.x,pb0.y,pb0.z,pb0.w,pb1.x,pb1.y,pb1.z,pb1.w};
    #pragma unroll
    for (int i = 0; i < 4; i++) {
        float r[8];
        #pragma unroll
        for (int j = 0; j < 4; j++) {
            float lo, hi; up2(acc[i][j], lo, hi);
            r[2*j] = lo + bb[2*j]; r[2*j+1] = hi + bb[2*j+1];
        }
        float* op = out + ((size_t)tok0 + t_m*4 + i)*128 + t_n*8;
        *(float4*)op     = make_float4(r[0], r[1], r[2], r[3]);
        *(float4*)(op+4) = make_float4(r[4], r[5], r[6], r[7]);
    }
}

// ---------------- streams/events (module init, reused every capture) ---------
struct LaunchRes {
    cudaStream_t s1 = 0, s2 = 0;
    cudaEvent_t evRoot = 0, evA = 0, evB = 0, evE = 0;
    bool ok = false;
    LaunchRes() {
        cudaFuncSetAttribute(kA_win,   cudaFuncAttributeMaxDynamicSharedMemorySize, 66560);
        cudaFuncSetAttribute(kB_bra,   cudaFuncAttributeMaxDynamicSharedMemorySize, 66560);
        cudaFuncSetAttribute(kD_attn,  cudaFuncAttributeMaxDynamicSharedMemorySize, 32768);
        cudaFuncSetAttribute(kE_lepe,  cudaFuncAttributeMaxDynamicSharedMemorySize, 57344);
        cudaFuncSetAttribute(kF1_caqkv,cudaFuncAttributeMaxDynamicSharedMemorySize, 100352);
        cudaFuncSetAttribute(kF23,     cudaFuncAttributeMaxDynamicSharedMemorySize, 67584);
        cudaFuncSetAttribute(kF4_out,  cudaFuncAttributeMaxDynamicSharedMemorySize, 76800);
        bool good = true;
        good &= cudaStreamCreateWithFlags(&s1, cudaStreamNonBlocking) == cudaSuccess;
        good &= cudaStreamCreateWithFlags(&s2, cudaStreamNonBlocking) == cudaSuccess;
        good &= cudaEventCreateWithFlags(&evRoot, cudaEventDisableTiming) == cudaSuccess;
        good &= cudaEventCreateWithFlags(&evA, cudaEventDisableTiming) == cudaSuccess;
        good &= cudaEventCreateWithFlags(&evB, cudaEventDisableTiming) == cudaSuccess;
        good &= cudaEventCreateWithFlags(&evE, cudaEventDisableTiming) == cudaSuccess;
        ok = good;
    }
};
static LaunchRes g_res;

// ---------------- launch ------------------------------------------------------
extern "C" void kernel_launch(void* const* d_in, const int* in_sizes, int n_in,
                              void* d_out, int out_size) {
    const float* x         = (const float*)d_in[0];
    const float* wqkv_w    = (const float*)d_in[1];
    const float* wqkv_b    = (const float*)d_in[2];
    const float* bqkv_w    = (const float*)d_in[3];
    const float* bqkv_b    = (const float*)d_in[4];
    const float* lepe_w    = (const float*)d_in[5];
    const float* lepe_b    = (const float*)d_in[6];
    const float* ca_qkv_w  = (const float*)d_in[7];
    const float* ca_qkv_b  = (const float*)d_in[8];
    const float* ca_temp   = (const float*)d_in[9];
    const float* ca_proj_w = (const float*)d_in[10];
    const float* ca_proj_b = (const float*)d_in[11];
    float* out = (float*)d_out;

    if (g_res.ok) {
        cudaEventRecord(g_res.evRoot, 0);
        cudaStreamWaitEvent(g_res.s1, g_res.evRoot, 0);
        kA_win<<<1024, 256, 66560, g_res.s1>>>(x, wqkv_w, wqkv_b);
        cudaEventRecord(g_res.evA, g_res.s1);

        kB_bra<<<1024, 256, 66560>>>(x, bqkv_w, bqkv_b);
        cudaEventRecord(g_res.evB, 0);

        cudaStreamWaitEvent(g_res.s2, g_res.evA, 0);
        cudaStreamWaitEvent(g_res.s2, g_res.evB, 0);
        kE_lepe<<<1024, 256, 57344, g_res.s2>>>(lepe_w, lepe_b);
        cudaEventRecord(g_res.evE, g_res.s2);

        kC_route<<<1024, 256>>>();
        kD_attn <<<2048, 128, 32768>>>();

        cudaStreamWaitEvent(0, g_res.evA, 0);
        cudaStreamWaitEvent(0, g_res.evE, 0);
        kF1_caqkv<<<1024, 256, 100352>>>(ca_qkv_w, ca_qkv_b);
        kF23     <<<1024, 256, 67584>>>();
        kF3b     <<<32, 256>>>(ca_temp);
        kF4_out  <<<1024, 256, 76800>>>(ca_proj_w, ca_proj_b, out);
    } else {
        kA_win   <<<1024, 256, 66560>>>(x, wqkv_w, wqkv_b);
        kB_bra   <<<1024, 256, 66560>>>(x, bqkv_w, bqkv_b);
        kC_route <<<1024, 256>>>();
        kD_attn  <<<2048, 128, 32768>>>();
        kE_lepe  <<<1024, 256, 57344>>>(lepe_w, lepe_b);
        kF1_caqkv<<<1024, 256, 100352>>>(ca_qkv_w, ca_qkv_b);
        kF23     <<<1024, 256, 67584>>>();
        kF3b     <<<32, 256>>>(ca_temp);
        kF4_out  <<<1024, 256, 76800>>>(ca_proj_w, ca_proj_b, out);
    }
}

// round 16
// speedup vs baseline: 1.0531x; 1.0531x over previous
#include <cuda_runtime.h>
#include <cuda_fp16.h>
#include <math.h>

#define BB   4
#define LL   16384
#define SCALE 0.08838834764831845f   // 128^-0.5

typedef unsigned long long ull;
typedef ulonglong2 ull2;

__device__ __forceinline__ ull pk2(float a, float b) {
    ull r; asm("mov.b64 %0,{%1,%2};" : "=l"(r) : "f"(a), "f"(b)); return r;
}
__device__ __forceinline__ ull dup2(float a) { return pk2(a, a); }
__device__ __forceinline__ void up2(ull v, float& a, float& b) {
    asm("mov.b64 {%0,%1},%2;" : "=f"(a), "=f"(b) : "l"(v));
}
__device__ __forceinline__ ull fma2(ull a, ull b, ull c) {
    ull d; asm("fma.rn.f32x2 %0,%1,%2,%3;" : "=l"(d) : "l"(a), "l"(b), "l"(c)); return d;
}
__device__ __forceinline__ ull mul2(ull a, ull b) {
    ull d; asm("mul.rn.f32x2 %0,%1,%2;" : "=l"(d) : "l"(a), "l"(b)); return d;
}
__device__ __forceinline__ float hadd2(ull v) { float a, b; up2(v, a, b); return a + b; }

// ---------------- scratch ----------------------------------------------------
__device__ __align__(16) float  g_winv[BB*256*64*64];   // (b,r,t,c) window V
__device__ __align__(16) float  g_vtok[BB*256*64*64];   // (b,r,t,c) bra V token-major
__device__ __align__(16) float  g_qb  [BB*8*256*64*8];  // (b,h,r,t,d) PRE-SCALED
__device__ __align__(16) __half g_kh  [BB*8*256*64*8];  // (b,h,r,t,d) fp16 k
__device__ __align__(16) float  g_vb  [BB*8*256*64*8];
__device__ __align__(16) float  g_qr  [BB*256*64];
__device__ __align__(16) float  g_krT [BB*64*256];      // channel-major pooled k
__device__ int   g_idx [BB*256*4];
__device__ __align__(16) float g_mid [(size_t)BB*LL*128];   // attention outputs
__device__ __align__(16) float g_lepe[(size_t)BB*LL*128];   // lepe (added in kF1)
__device__ __align__(16) float g_cq  [(size_t)BB*LL*128];   // token-major
__device__ __align__(16) float g_ck  [(size_t)BB*LL*128];
__device__ __align__(16) float g_cv  [(size_t)BB*LL*128];
__device__ float g_norm2[2*BB*128];
__device__ float g_gram[32*256];
__device__ float g_attn[32*256];

// ---------------- kA: window QKV GEMM + window attention --------------------
__global__ void kA_win(const float* __restrict__ x, const float* __restrict__ w,
                       const float* __restrict__ bias) {
    extern __shared__ float sm[];
    float* s_xT  = sm;            // 64 k x 68 m
    float* s_w   = sm + 64*68;    // 64 x 192 (reused as s_qkv)
    float* s_qkv = s_w;
    int wid = blockIdx.x;
    int b = wid >> 8, r = wid & 255, ry = r >> 4, rx = r & 15;
    int tid = threadIdx.x;

    for (int i = tid; i < 4096; i += 256) {
        int t = i >> 6, c = i & 63;
        int y = ry*8 + (t >> 3), xx = rx*8 + (t & 7);
        s_xT[c*68 + t] = x[(((size_t)b*128 + y)*128 + xx)*128 + c];
    }
    for (int i = tid; i < 12288; i += 256) s_w[i] = w[i];
    __syncthreads();

    int t_m = tid & 15, t_n = tid >> 4;     // m = t_m*4, n = t_n*12
    ull acc[4][6];
    #pragma unroll
    for (int i = 0; i < 4; i++)
        #pragma unroll
        for (int j = 0; j < 6; j++) acc[i][j] = 0ull;
    for (int k = 0; k < 64; k++) {
        float4 a4 = *(const float4*)(s_xT + k*68 + t_m*4);
        ull a0 = dup2(a4.x), a1 = dup2(a4.y), a2 = dup2(a4.z), a3 = dup2(a4.w);
        const ull2* bp = (const ull2*)(s_w + k*192 + t_n*12);
        ull2 B0 = bp[0], B1 = bp[1], B2 = bp[2];
        ull b0=B0.x, b1=B0.y, b2=B1.x, b3=B1.y, b4=B2.x, b5=B2.y;
        acc[0][0]=fma2(a0,b0,acc[0][0]); acc[0][1]=fma2(a0,b1,acc[0][1]);
        acc[0][2]=fma2(a0,b2,acc[0][2]); acc[0][3]=fma2(a0,b3,acc[0][3]);
        acc[0][4]=fma2(a0,b4,acc[0][4]); acc[0][5]=fma2(a0,b5,acc[0][5]);
        acc[1][0]=fma2(a1,b0,acc[1][0]); acc[1][1]=fma2(a1,b1,acc[1][1]);
        acc[1][2]=fma2(a1,b2,acc[1][2]); acc[1][3]=fma2(a1,b3,acc[1][3]);
        acc[1][4]=fma2(a1,b4,acc[1][4]); acc[1][5]=fma2(a1,b5,acc[1][5]);
        acc[2][0]=fma2(a2,b0,acc[2][0]); acc[2][1]=fma2(a2,b1,acc[2][1]);
        acc[2][2]=fma2(a2,b2,acc[2][2]); acc[2][3]=fma2(a2,b3,acc[2][3]);
        acc[2][4]=fma2(a2,b4,acc[2][4]); acc[2][5]=fma2(a2,b5,acc[2][5]);
        acc[3][0]=fma2(a3,b0,acc[3][0]); acc[3][1]=fma2(a3,b1,acc[3][1]);
        acc[3][2]=fma2(a3,b2,acc[3][2]); acc[3][3]=fma2(a3,b3,acc[3][3]);
        acc[3][4]=fma2(a3,b4,acc[3][4]); acc[3][5]=fma2(a3,b5,acc[3][5]);
    }
    __syncthreads();
    {
        float bb[12];
        #pragma unroll
        for (int j = 0; j < 12; j++) bb[j] = __ldg(bias + t_n*12 + j);
        #pragma unroll
        for (int i = 0; i < 4; i++)
            #pragma unroll
            for (int j = 0; j < 6; j++) {
                float lo, hi; up2(acc[i][j], lo, hi);
                s_qkv[(t_m*4+i)*192 + t_n*12 + 2*j]     = lo + bb[2*j];
                s_qkv[(t_m*4+i)*192 + t_n*12 + 2*j + 1] = hi + bb[2*j+1];
            }
    }
    __syncthreads();

    size_t base = (size_t)wid * 4096;
    for (int i = tid; i < 4096; i += 256) {
        int t = i >> 6, c = i & 63;
        g_winv[base + i] = s_qkv[t*192 + 128 + c];
    }

    // attention: warp = head, 2 q-rows per thread
    int h = tid >> 5, lane = tid & 31;
    ull sc = dup2(SCALE);
    const ull2* qp0 = (const ull2*)(s_qkv + lane*192 + h*8);
    const ull2* qp1 = (const ull2*)(s_qkv + (lane+32)*192 + h*8);
    ull2 Q0a = qp0[0], Q0b = qp0[1], Q1a = qp1[0], Q1b = qp1[1];
    ull q0[4] = {mul2(Q0a.x,sc), mul2(Q0a.y,sc), mul2(Q0b.x,sc), mul2(Q0b.y,sc)};
    ull q1[4] = {mul2(Q1a.x,sc), mul2(Q1a.y,sc), mul2(Q1b.x,sc), mul2(Q1b.y,sc)};
    float ssum0 = 0.f, ssum1 = 0.f;
    ull a0[4] = {0,0,0,0}, a1[4] = {0,0,0,0};
    #pragma unroll 2
    for (int j = 0; j < 64; j++) {
        const ull2* kp = (const ull2*)(s_qkv + j*192 + 64 + h*8);
        ull2 K0 = kp[0], K1 = kp[1];
        ull s20 = fma2(q0[0],K0.x, fma2(q0[1],K0.y, fma2(q0[2],K1.x, mul2(q0[3],K1.y))));
        ull s21 = fma2(q1[0],K0.x, fma2(q1[1],K0.y, fma2(q1[2],K1.x, mul2(q1[3],K1.y))));
        float e0 = __expf(hadd2(s20));
        float e1 = __expf(hadd2(s21));
        ssum0 += e0; ssum1 += e1;
        ull e0d = dup2(e0), e1d = dup2(e1);
        const ull2* vp = (const ull2*)(s_qkv + j*192 + 128 + h*8);
        ull2 V0 = vp[0], V1 = vp[1];
        a0[0]=fma2(e0d,V0.x,a0[0]); a0[1]=fma2(e0d,V0.y,a0[1]);
        a0[2]=fma2(e0d,V1.x,a0[2]); a0[3]=fma2(e0d,V1.y,a0[3]);
        a1[0]=fma2(e1d,V0.x,a1[0]); a1[1]=fma2(e1d,V0.y,a1[1]);
        a1[2]=fma2(e1d,V1.x,a1[2]); a1[3]=fma2(e1d,V1.y,a1[3]);
    }
    ull i0 = dup2(1.f/ssum0), i1 = dup2(1.f/ssum1);
    {
        int row = lane;
        int y = ry*8 + (row>>3), xx = rx*8 + (row&7);
        ull* mo = (ull*)(g_mid + ((size_t)b*LL + y*128 + xx)*128 + h*8);
        mo[0]=mul2(a0[0],i0); mo[1]=mul2(a0[1],i0); mo[2]=mul2(a0[2],i0); mo[3]=mul2(a0[3],i0);
        row = lane + 32;
        y = ry*8 + (row>>3); xx = rx*8 + (row&7);
        mo = (ull*)(g_mid + ((size_t)b*LL + y*128 + xx)*128 + h*8);
        mo[0]=mul2(a1[0],i1); mo[1]=mul2(a1[1],i1); mo[2]=mul2(a1[2],i1); mo[3]=mul2(a1[3],i1);
    }
}

// ---------------- kB: BRA QKV GEMM (head-major q/kh/v + token-major V) ------
__global__ void kB_bra(const float* __restrict__ x, const float* __restrict__ w,
                       const float* __restrict__ bias) {
    extern __shared__ float sm[];
    float* s_xT  = sm;
    float* s_w   = sm + 64*68;
    float* s_qkv = s_w;
    int wid = blockIdx.x;
    int b = wid >> 8, r = wid & 255, ry = r >> 4, rx = r & 15;
    int tid = threadIdx.x;

    for (int i = tid; i < 4096; i += 256) {
        int t = i >> 6, c = i & 63;
        int y = ry*8 + (t >> 3), xx = rx*8 + (t & 7);
        s_xT[c*68 + t] = x[(((size_t)b*128 + y)*128 + xx)*128 + 64 + c];
    }
    for (int i = tid; i < 12288; i += 256) s_w[i] = w[i];
    __syncthreads();

    int t_m = tid & 15, t_n = tid >> 4;
    ull acc[4][6];
    #pragma unroll
    for (int i = 0; i < 4; i++)
        #pragma unroll
        for (int j = 0; j < 6; j++) acc[i][j] = 0ull;
    for (int k = 0; k < 64; k++) {
        float4 a4 = *(const float4*)(s_xT + k*68 + t_m*4);
        ull a0 = dup2(a4.x), a1 = dup2(a4.y), a2 = dup2(a4.z), a3 = dup2(a4.w);
        const ull2* bp = (const ull2*)(s_w + k*192 + t_n*12);
        ull2 B0 = bp[0], B1 = bp[1], B2 = bp[2];
        ull b0=B0.x, b1=B0.y, b2=B1.x, b3=B1.y, b4=B2.x, b5=B2.y;
        acc[0][0]=fma2(a0,b0,acc[0][0]); acc[0][1]=fma2(a0,b1,acc[0][1]);
        acc[0][2]=fma2(a0,b2,acc[0][2]); acc[0][3]=fma2(a0,b3,acc[0][3]);
        acc[0][4]=fma2(a0,b4,acc[0][4]); acc[0][5]=fma2(a0,b5,acc[0][5]);
        acc[1][0]=fma2(a1,b0,acc[1][0]); acc[1][1]=fma2(a1,b1,acc[1][1]);
        acc[1][2]=fma2(a1,b2,acc[1][2]); acc[1][3]=fma2(a1,b3,acc[1][3]);
        acc[1][4]=fma2(a1,b4,acc[1][4]); acc[1][5]=fma2(a1,b5,acc[1][5]);
        acc[2][0]=fma2(a2,b0,acc[2][0]); acc[2][1]=fma2(a2,b1,acc[2][1]);
        acc[2][2]=fma2(a2,b2,acc[2][2]); acc[2][3]=fma2(a2,b3,acc[2][3]);
        acc[2][4]=fma2(a2,b4,acc[2][4]); acc[2][5]=fma2(a2,b5,acc[2][5]);
        acc[3][0]=fma2(a3,b0,acc[3][0]); acc[3][1]=fma2(a3,b1,acc[3][1]);
        acc[3][2]=fma2(a3,b2,acc[3][2]); acc[3][3]=fma2(a3,b3,acc[3][3]);
        acc[3][4]=fma2(a3,b4,acc[3][4]); acc[3][5]=fma2(a3,b5,acc[3][5]);
    }
    __syncthreads();
    {
        float bb[12];
        #pragma unroll
        for (int j = 0; j < 12; j++) bb[j] = __ldg(bias + t_n*12 + j);
        #pragma unroll
        for (int i = 0; i < 4; i++)
            #pragma unroll
            for (int j = 0; j < 6; j++) {
                float lo, hi; up2(acc[i][j], lo, hi);
                s_qkv[(t_m*4+i)*192 + t_n*12 + 2*j]     = lo + bb[2*j];
                s_qkv[(t_m*4+i)*192 + t_n*12 + 2*j + 1] = hi + bb[2*j+1];
            }
    }
    __syncthreads();

    for (int i = tid; i < 4096; i += 256) {
        int hh = i >> 9, rest = i & 511;
        int t = rest >> 3, d = rest & 7;
        size_t off = ((size_t)(b*8 + hh)*256 + r)*512 + rest;
        g_qb[off] = s_qkv[t*192 + hh*8 + d] * SCALE;            // pre-scaled
        g_kh[off] = __float2half(s_qkv[t*192 + 64 + hh*8 + d]); // fp16 k
        g_vb[off] = s_qkv[t*192 + 128 + hh*8 + d];
    }
    size_t base = (size_t)wid * 4096;
    for (int i = tid; i < 4096; i += 256) {
        int t = i >> 6, c = i & 63;
        g_vtok[base + i] = s_qkv[t*192 + 128 + c];
    }
    if (tid < 64) {
        float sq = 0.f, sk = 0.f;
        for (int t = 0; t < 64; t++) {
            sq += s_qkv[t*192 + tid];
            sk += s_qkv[t*192 + 64 + tid];
        }
        g_qr[wid*64 + tid] = sq * 0.015625f;
        g_krT[((size_t)b*64 + tid)*256 + r] = sk * 0.015625f;
    }
}

// ---------------- kC: routing (coalesced) + warp-register top-4 + zeroing ---
__global__ void kC_route() {
    __shared__ float s_q[64];
    __shared__ float s_a[256];
    int bx = blockIdx.x;
    int b = bx >> 8, i = bx & 255;
    int tid = threadIdx.x;
    if (bx < 32) g_gram[bx*256 + tid] = 0.f;
    else if (bx < 36) g_norm2[(bx-32)*256 + tid] = 0.f;
    if (tid < 64) s_q[tid] = g_qr[(b*256 + i)*64 + tid];
    __syncthreads();
    const float* krT = g_krT + (size_t)b*64*256 + tid;   // lane-coalesced
    float a = 0.f;
    #pragma unroll 8
    for (int c = 0; c < 64; c++) a += s_q[c]*krT[c*256];
    s_a[tid] = a;
    __syncthreads();
    if (tid < 32) {
        float v[8];
        #pragma unroll
        for (int j = 0; j < 8; j++) v[j] = s_a[tid + j*32];
        #pragma unroll
        for (int s = 0; s < 4; s++) {
            float bv = v[0]; int bj = 0;
            #pragma unroll
            for (int j = 1; j < 8; j++)
                if (v[j] > bv) { bv = v[j]; bj = j; }
            int bidx = tid + bj*32;
            #pragma unroll
            for (int off = 16; off > 0; off >>= 1) {
                float ov = __shfl_down_sync(0xffffffffu, bv, off);
                int   oi = __shfl_down_sync(0xffffffffu, bidx, off);
                if (ov > bv || (ov == bv && oi < bidx)) { bv = ov; bidx = oi; }
            }
            bidx = __shfl_sync(0xffffffffu, bidx, 0);
            if (tid == 0) g_idx[(b*256 + i)*4 + s] = bidx;
            if ((bidx & 31) == tid) v[bidx >> 5] = -INFINITY;
        }
    }
}

// ---------------- kD: BRA attn (4 heads/block, fp16 k, 2 q/thread) ----------
__global__ void kD_attn() {
    extern __shared__ char smd[];
    __half* s_k = (__half*)smd;              // 4*256*8 halfs = 16KB
    float*  s_v = (float*)(smd + 16384);     // 4*256*8 floats = 32KB
    __shared__ int s_i4[4];
    int bid = blockIdx.x;                    // 2048: b(4) x hp(2) x r(256)
    int b = bid >> 9, hp = (bid >> 8) & 1, r = bid & 255;
    int tid = threadIdx.x;                   // 128
    if (tid < 4) s_i4[tid] = g_idx[(b*256 + r)*4 + tid];
    __syncthreads();
    for (int i = tid; i < 1024; i += 128) {  // k: 16B per key
        int hl = i >> 8, key = i & 255;
        int reg = s_i4[key >> 6], t = key & 63;
        size_t off = ((size_t)(b*8 + hp*4 + hl)*256 + reg)*512 + t*8;
        *(uint4*)(s_k + (size_t)i*8) = *(const uint4*)(g_kh + off);
    }
    for (int i = tid; i < 2048; i += 128) {  // v: 2x16B per key
        int hl = i >> 9, rem = i & 511;
        int key = rem >> 1, d4 = rem & 1;
        int reg = s_i4[key >> 6], t = key & 63;
        size_t off = ((size_t)(b*8 + hp*4 + hl)*256 + reg)*512 + t*8 + d4*4;
        *(float4*)(s_v + (size_t)i*4) = *(const float4*)(g_vb + off);
    }
    __syncthreads();
    int hl = tid >> 5, lane = tid & 31;      // warp = head; rows lane, lane+32
    int h = hp*4 + hl;
    size_t qbase = ((size_t)(b*8 + h)*256 + r)*512;
    const float2* qa = (const float2*)(g_qb + qbase + lane*8);       // pre-scaled
    const float2* qb2 = (const float2*)(g_qb + qbase + (lane+32)*8);
    __half2 qh0[4], qh1[4];
    #pragma unroll
    for (int d = 0; d < 4; d++) {
        qh0[d] = __float22half2_rn(qa[d]);
        qh1[d] = __float22half2_rn(qb2[d]);
    }
    const uint4* kp = (const uint4*)(s_k + (size_t)hl*2048);
    const ull2*  vp = (const ull2*)(s_v + (size_t)hl*2048);
    float ss0 = 0.f, ss1 = 0.f;
    ull a00=0,a01=0,a02=0,a03=0, a10=0,a11=0,a12=0,a13=0;
    #pragma unroll 2
    for (int j = 0; j < 256; j++) {
        uint4 kk = kp[j];
        __half2 k0 = *(__half2*)&kk.x, k1 = *(__half2*)&kk.y,
                k2 = *(__half2*)&kk.z, k3 = *(__half2*)&kk.w;
        __half2 h0 = __hfma2(qh0[1], k1, __hmul2(qh0[0], k0));
        h0 = __hfma2(qh0[3], k3, __hfma2(qh0[2], k2, h0));
        __half2 h1 = __hfma2(qh1[1], k1, __hmul2(qh1[0], k0));
        h1 = __hfma2(qh1[3], k3, __hfma2(qh1[2], k2, h1));
        float2 f0 = __half22float2(h0);
        float2 f1 = __half22float2(h1);
        float e0 = __expf(f0.x + f0.y);
        float e1 = __expf(f1.x + f1.y);
        ss0 += e0; ss1 += e1;
        ull e0d = dup2(e0), e1d = dup2(e1);
        ull2 V0 = vp[j*2], V1 = vp[j*2 + 1];
        a00 = fma2(e0d, V0.x, a00); a01 = fma2(e0d, V0.y, a01);
        a02 = fma2(e0d, V1.x, a02); a03 = fma2(e0d, V1.y, a03);
        a10 = fma2(e1d, V0.x, a10); a11 = fma2(e1d, V0.y, a11);
        a12 = fma2(e1d, V1.x, a12); a13 = fma2(e1d, V1.y, a13);
    }
    ull i0 = dup2(1.f/ss0), i1 = dup2(1.f/ss1);
    {
        int row = lane;
        int y = (r >> 4)*8 + (row >> 3), xx = (r & 15)*8 + (row & 7);
        ull* mo = (ull*)(g_mid + ((size_t)b*LL + y*128 + xx)*128 + 64 + h*8);
        mo[0]=mul2(a00,i0); mo[1]=mul2(a01,i0); mo[2]=mul2(a02,i0); mo[3]=mul2(a03,i0);
        row = lane + 32;
        y = (r >> 4)*8 + (row >> 3); xx = (r & 15)*8 + (row & 7);
        mo = (ull*)(g_mid + ((size_t)b*LL + y*128 + xx)*128 + 64 + h*8);
        mo[0]=mul2(a10,i1); mo[1]=mul2(a11,i1); mo[2]=mul2(a12,i1); mo[3]=mul2(a13,i1);
    }
}

// ---------------- kE: depthwise 3x3 LEPE, smem-tiled (writes g_lepe) --------
__global__ void kE_lepe(const float* __restrict__ lw, const float* __restrict__ lb) {
    extern __shared__ float se[];
    float* s_v  = se;             // vtok patch: 100 pos x 64 ch = 6400
    float* s_wi = se + 6400;      // winv patch: 6400
    float* s_lw = se + 12800;     // 128*9 = 1152
    float* s_lb = se + 13952;     // 128
    int bid = blockIdx.x;         // 1024 = b(4) x r(256)
    int b = bid >> 8, r = bid & 255, ry = r >> 4, rx = r & 15;
    int tid = threadIdx.x;        // 256

    for (int i = tid; i < 1152; i += 256) s_lw[i] = lw[i];
    if (tid < 128) s_lb[tid] = lb[tid];
    for (int i = tid; i < 3200; i += 256) {   // 2 arrays x 100 pos x 16 float4
        int half = i >= 1600;
        int rem = half ? i - 1600 : i;
        int pos = rem >> 4, f4 = rem & 15;
        int py = pos / 10, px = pos - py*10;
        int y = ry*8 - 1 + py, x = rx*8 - 1 + px;
        float4 val = make_float4(0.f, 0.f, 0.f, 0.f);
        if (y >= 0 && y < 128 && x >= 0 && x < 128) {
            int rr = (y >> 3)*16 + (x >> 3), tt = (y & 7)*8 + (x & 7);
            const float* src = half ? g_winv : g_vtok;
            val = *(const float4*)(src + ((size_t)(b*256 + rr))*4096 + tt*64 + f4*4);
        }
        float* dst = half ? s_wi : s_v;
        *(float4*)(dst + pos*64 + f4*4) = val;
    }
    __syncthreads();

    for (int i = tid; i < 8192; i += 256) {   // 64 tokens x 128 ch
        int tok = i >> 7, c = i & 127;
        int iy = tok >> 3, ix = tok & 7;
        const float* s_src = (c < 64) ? s_v : s_wi;
        int cc = c & 63;
        float acc = s_lb[c];
        const float* wr = s_lw + c*9;
        #pragma unroll
        for (int ky = 0; ky < 3; ky++)
            #pragma unroll
            for (int kx = 0; kx < 3; kx++)
                acc += s_src[((iy+ky)*10 + (ix+kx))*64 + cc] * wr[ky*3 + kx];
        int y = ry*8 + iy, x = rx*8 + ix;
        g_lepe[((size_t)b*LL + y*128 + x)*128 + c] = acc;
    }
}

// ---------------- kF1: CA-qkv GEMM, A = g_mid + g_lepe, single launch -------
__global__ void kF1_caqkv(const float* __restrict__ w, const float* __restrict__ bias) {
    extern __shared__ float sm[];
    float* AsT = sm;          // [128 k][68 m]
    float* Bs  = sm + 8704;   // [128 k][128 n] (reused as Cs)
    float* Cs  = Bs;
    int m0 = blockIdx.x * 64;
    int tid = threadIdx.x;

    for (int i = tid; i < 8192; i += 256) {
        int t = i >> 7, k = i & 127;
        size_t go = (size_t)(m0 + t)*128 + k;
        AsT[k*68 + t] = g_mid[go] + g_lepe[go];
    }

    int t_m = tid & 15, t_n = tid >> 4;
    for (int nb = 0; nb < 3; nb++) {
        __syncthreads();
        for (int i = tid; i < 16384; i += 256) {
            int k = i >> 7, n = i & 127;
            Bs[i] = w[k*384 + nb*128 + n];
        }
        __syncthreads();

        ull acc[4][4];
        #pragma unroll
        for (int i = 0; i < 4; i++)
            #pragma unroll
            for (int j = 0; j < 4; j++) acc[i][j] = 0ull;
        #pragma unroll 4
        for (int k = 0; k < 128; k++) {
            float4 a4 = *(const float4*)(AsT + k*68 + t_m*4);
            ull a0 = dup2(a4.x), a1 = dup2(a4.y), a2 = dup2(a4.z), a3 = dup2(a4.w);
            const ull2* bp = (const ull2*)(Bs + k*128 + t_n*8);
            ull2 B0 = bp[0], B1 = bp[1];
            ull b0=B0.x, b1=B0.y, b2=B1.x, b3=B1.y;
            acc[0][0]=fma2(a0,b0,acc[0][0]); acc[0][1]=fma2(a0,b1,acc[0][1]);
            acc[0][2]=fma2(a0,b2,acc[0][2]); acc[0][3]=fma2(a0,b3,acc[0][3]);
            acc[1][0]=fma2(a1,b0,acc[1][0]); acc[1][1]=fma2(a1,b1,acc[1][1]);
            acc[1][2]=fma2(a1,b2,acc[1][2]); acc[1][3]=fma2(a1,b3,acc[1][3]);
            acc[2][0]=fma2(a2,b0,acc[2][0]); acc[2][1]=fma2(a2,b1,acc[2][1]);
            acc[2][2]=fma2(a2,b2,acc[2][2]); acc[2][3]=fma2(a2,b3,acc[2][3]);
            acc[3][0]=fma2(a3,b0,acc[3][0]); acc[3][1]=fma2(a3,b1,acc[3][1]);
            acc[3][2]=fma2(a3,b2,acc[3][2]); acc[3][3]=fma2(a3,b3,acc[3][3]);
        }
        __syncthreads();

        {
            float bb[8];
            #pragma unroll
            for (int j = 0; j < 8; j++) bb[j] = __ldg(bias + nb*128 + t_n*8 + j);
            #pragma unroll
            for (int i = 0; i < 4; i++)
                #pragma unroll
                for (int j = 0; j < 4; j++) {
                    float lo, hi; up2(acc[i][j], lo, hi);
                    Cs[(t_m*4+i)*132 + t_n*8 + 2*j]     = lo + bb[2*j];
                    Cs[(t_m*4+i)*132 + t_n*8 + 2*j + 1] = hi + bb[2*j+1];
                }
        }
        __syncthreads();
        float* dst = (nb == 0) ? g_cq : (nb == 1) ? g_ck : g_cv;
        for (int i = tid; i < 2048; i += 256) {
            int m = i >> 5, nf = i & 31;
            *(float4*)(dst + (size_t)(m0 + m)*128 + nf*4) = *(const float4*)(Cs + m*132 + nf*4);
        }
    }
}

// ---------------- kF23: norms + grams, channel-major tiles (pad 66) ---------
__global__ void kF23() {
    extern __shared__ float sm[];
    float* qs = sm;            // 128 ch x 66 t
    float* ks = sm + 8448;
    int bid = blockIdx.x;      // 1024 = b(4) x chunk(256)
    int b = bid >> 8, ch = bid & 255;
    int l0 = ch*64;
    int tid = threadIdx.x;
    const float4* qsrc = (const float4*)(g_cq + ((size_t)b*LL + l0)*128);
    const float4* ksrc = (const float4*)(g_ck + ((size_t)b*LL + l0)*128);
    for (int i = tid; i < 2048; i += 256) {
        int t = i >> 5, nf = i & 31;
        float4 q4 = qsrc[t*32 + nf];
        float4 k4 = ksrc[t*32 + nf];
        int c = nf*4;
        qs[(c+0)*66 + t] = q4.x; qs[(c+1)*66 + t] = q4.y;
        qs[(c+2)*66 + t] = q4.z; qs[(c+3)*66 + t] = q4.w;
        ks[(c+0)*66 + t] = k4.x; ks[(c+1)*66 + t] = k4.y;
        ks[(c+2)*66 + t] = k4.z; ks[(c+3)*66 + t] = k4.w;
    }
    __syncthreads();
    {
        const ull* bp = (tid < 128) ? (const ull*)(qs + tid*66)
                                    : (const ull*)(ks + (tid - 128)*66);
        ull acc2 = 0ull;
        #pragma unroll 8
        for (int t2 = 0; t2 < 32; t2++) { ull v = bp[t2]; acc2 = fma2(v, v, acc2); }
        atomicAdd(&g_norm2[((tid < 128) ? 0 : 512) + b*128 + (tid & 127)], hadd2(acc2));
    }
    int d = tid >> 4, e = tid & 15;
    #pragma unroll
    for (int h = 0; h < 8; h++) {
        const ull* qp2 = (const ull*)(qs + (h*16 + d)*66);
        const ull* kp2 = (const ull*)(ks + (h*16 + e)*66);
        ull acc2 = 0ull;
        #pragma unroll 8
        for (int t2 = 0; t2 < 32; t2++) acc2 = fma2(qp2[t2], kp2[t2], acc2);
        atomicAdd(&g_gram[(b*8 + h)*256 + tid], hadd2(acc2));
    }
}

// ---------------- kF3b: normalize + softmax ----------------------------------
__global__ void kF3b(const float* __restrict__ temp) {
    __shared__ float smm[256];
    int bh = blockIdx.x;
    int b = bh >> 3, h = bh & 7;
    int tid = threadIdx.x;
    int d = tid >> 4, e = tid & 15;
    int rowq = b*128 + h*16;
    float nq = fmaxf(sqrtf(g_norm2[rowq + d]), 1e-12f);
    float nk = fmaxf(sqrtf(g_norm2[512 + rowq + e]), 1e-12f);
    smm[tid] = g_gram[bh*256 + tid] / (nq*nk) * __ldg(temp + h);
    __syncthreads();
    if (tid < 16) {
        float mx = -INFINITY;
        for (int j = 0; j < 16; j++) mx = fmaxf(mx, smm[tid*16 + j]);
        float ssum = 0.f, ex[16];
        for (int j = 0; j < 16; j++) { ex[j] = __expf(smm[tid*16 + j] - mx); ssum += ex[j]; }
        float inv = 1.f/ssum;
        for (int j = 0; j < 16; j++) g_attn[bh*256 + tid*16 + j] = ex[j]*inv;
    }
}

// ---------------- kF4: cout mix (attn pad 18) + 128x128 projection ----------
__global__ void kF4_out(const float* __restrict__ pw, const float* __restrict__ pb,
                        float* __restrict__ out) {
    extern __shared__ float sm[];
    float* s_attn = sm;           // 128 ch x 18
    float* s_cv   = sm + 2304;    // 64 x 128
    float* coutT  = sm + 10496;   // 128 k x 68 m
    int tok0 = blockIdx.x * 64;
    int b = tok0 >> 14;
    int tid = threadIdx.x;
    for (int i = tid; i < 2048; i += 256)
        s_attn[(i >> 4)*18 + (i & 15)] = g_attn[b*2048 + i];
    for (int i = tid; i < 8192; i += 256) s_cv[i] = g_cv[(size_t)tok0*128 + i];
    __syncthreads();
    for (int i = tid; i < 8192; i += 256) {
        int m = i >> 7, chn = i & 127;
        int h = chn >> 4;
        const ull* ap  = (const ull*)(s_attn + chn*18);
        const ull2* cvp = (const ull2*)(s_cv + m*128 + h*16);
        ull2 C0 = cvp[0], C1 = cvp[1], C2 = cvp[2], C3 = cvp[3];
        ull acc = mul2(ap[0], C0.x);
        acc = fma2(ap[1], C0.y, acc);
        acc = fma2(ap[2], C1.x, acc);
        acc = fma2(ap[3], C1.y, acc);
        acc = fma2(ap[4], C2.x, acc);
        acc = fma2(ap[5], C2.y, acc);
        acc = fma2(ap[6], C3.x, acc);
        acc = fma2(ap[7], C3.y, acc);
        coutT[chn*68 + m] = hadd2(acc);
    }
    __syncthreads();
    int t_m = tid & 15, t_n = tid >> 4;
    ull acc[4][4];
    #pragma unroll
    for (int i = 0; i < 4; i++)
        #pragma unroll
        for (int j = 0; j < 4; j++) acc[i][j] = 0ull;
    #pragma unroll 4
    for (int k = 0; k < 128; k++) {
        float4 a4 = *(const float4*)(coutT + k*68 + t_m*4);
        ull a0 = dup2(a4.x), a1 = dup2(a4.y), a2 = dup2(a4.z), a3 = dup2(a4.w);
        float4 w0 = __ldg((const float4*)(pw + k*128 + t_n*8));
        float4 w1 = __ldg((const float4*)(pw + k*128 + t_n*8 + 4));
        ull b0 = pk2(w0.x, w0.y), b1 = pk2(w0.z, w0.w);
        ull b2 = pk2(w1.x, w1.y), b3 = pk2(w1.z, w1.w);
        acc[0][0]=fma2(a0,b0,acc[0][0]); acc[0][1]=fma2(a0,b1,acc[0][1]);
        acc[0][2]=fma2(a0,b2,acc[0][2]); acc[0][3]=fma2(a0,b3,acc[0][3]);
        acc[1][0]=fma2(a1,b0,acc[1][0]); acc[1][1]=fma2(a1,b1,acc[1][1]);
        acc[1][2]=fma2(a1,b2,acc[1][2]); acc[1][3]=fma2(a1,b3,acc[1][3]);
        acc[2][0]=fma2(a2,b0,acc[2][0]); acc[2][1]=fma2(a2,b1,acc[2][1]);
        acc[2][2]=fma2(a2,b2,acc[2][2]); acc[2][3]=fma2(a2,b3,acc[2][3]);
        acc[3][0]=fma2(a3,b0,acc[3][0]); acc[3][1]=fma2(a3,b1,acc[3][1]);
        acc[3][2]=fma2(a3,b2,acc[3][2]); acc[3][3]=fma2(a3,b3,acc[3][3]);
    }
    float4 pb0 = __ldg((const float4*)(pb + t_n*8));
    float4 pb1 = __ldg((const float4*)(pb + t_n*8 + 4));
    float bb[8] = {pb0.x,pb0.y,pb0.z,pb0.w,pb1.x,pb1.y,pb1.z,pb1.w};
    #pragma unroll
    for (int i = 0; i < 4; i++) {
        float r[8];
        #pragma unroll
        for (int j = 0; j < 4; j++) {
            float lo, hi; up2(acc[i][j], lo, hi);
            r[2*j] = lo + bb[2*j]; r[2*j+1] = hi + bb[2*j+1];
        }
        float* op = out + ((size_t)tok0 + t_m*4 + i)*128 + t_n*8;
        *(float4*)op     = make_float4(r[0], r[1], r[2], r[3]);
        *(float4*)(op+4) = make_float4(r[4], r[5], r[6], r[7]);
    }
}

// ---------------- streams/events (module init, reused every capture) ---------
struct LaunchRes {
    cudaStream_t s1 = 0, s2 = 0;
    cudaEvent_t evRoot = 0, evA = 0, evB = 0, evE = 0;
    bool ok = false;
    LaunchRes() {
        cudaFuncSetAttribute(kA_win,   cudaFuncAttributeMaxDynamicSharedMemorySize, 66560);
        cudaFuncSetAttribute(kB_bra,   cudaFuncAttributeMaxDynamicSharedMemorySize, 66560);
        cudaFuncSetAttribute(kD_attn,  cudaFuncAttributeMaxDynamicSharedMemorySize, 49152);
        cudaFuncSetAttribute(kE_lepe,  cudaFuncAttributeMaxDynamicSharedMemorySize, 57344);
        cudaFuncSetAttribute(kF1_caqkv,cudaFuncAttributeMaxDynamicSharedMemorySize, 100352);
        cudaFuncSetAttribute(kF23,     cudaFuncAttributeMaxDynamicSharedMemorySize, 67584);
        cudaFuncSetAttribute(kF4_out,  cudaFuncAttributeMaxDynamicSharedMemorySize, 76800);
        bool good = true;
        good &= cudaStreamCreateWithFlags(&s1, cudaStreamNonBlocking) == cudaSuccess;
        good &= cudaStreamCreateWithFlags(&s2, cudaStreamNonBlocking) == cudaSuccess;
        good &= cudaEventCreateWithFlags(&evRoot, cudaEventDisableTiming) == cudaSuccess;
        good &= cudaEventCreateWithFlags(&evA, cudaEventDisableTiming) == cudaSuccess;
        good &= cudaEventCreateWithFlags(&evB, cudaEventDisableTiming) == cudaSuccess;
        good &= cudaEventCreateWithFlags(&evE, cudaEventDisableTiming) == cudaSuccess;
        ok = good;
    }
};
static LaunchRes g_res;

// ---------------- launch ------------------------------------------------------
extern "C" void kernel_launch(void* const* d_in, const int* in_sizes, int n_in,
                              void* d_out, int out_size) {
    const float* x         = (const float*)d_in[0];
    const float* wqkv_w    = (const float*)d_in[1];
    const float* wqkv_b    = (const float*)d_in[2];
    const float* bqkv_w    = (const float*)d_in[3];
    const float* bqkv_b    = (const float*)d_in[4];
    const float* lepe_w    = (const float*)d_in[5];
    const float* lepe_b    = (const float*)d_in[6];
    const float* ca_qkv_w  = (const float*)d_in[7];
    const float* ca_qkv_b  = (const float*)d_in[8];
    const float* ca_temp   = (const float*)d_in[9];
    const float* ca_proj_w = (const float*)d_in[10];
    const float* ca_proj_b = (const float*)d_in[11];
    float* out = (float*)d_out;

    if (g_res.ok) {
        cudaEventRecord(g_res.evRoot, 0);
        cudaStreamWaitEvent(g_res.s1, g_res.evRoot, 0);
        kA_win<<<1024, 256, 66560, g_res.s1>>>(x, wqkv_w, wqkv_b);
        cudaEventRecord(g_res.evA, g_res.s1);

        kB_bra<<<1024, 256, 66560>>>(x, bqkv_w, bqkv_b);
        cudaEventRecord(g_res.evB, 0);

        cudaStreamWaitEvent(g_res.s2, g_res.evA, 0);
        cudaStreamWaitEvent(g_res.s2, g_res.evB, 0);
        kE_lepe<<<1024, 256, 57344, g_res.s2>>>(lepe_w, lepe_b);
        cudaEventRecord(g_res.evE, g_res.s2);

        kC_route<<<1024, 256>>>();
        kD_attn <<<2048, 128, 49152>>>();

        cudaStreamWaitEvent(0, g_res.evA, 0);
        cudaStreamWaitEvent(0, g_res.evE, 0);
        kF1_caqkv<<<1024, 256, 100352>>>(ca_qkv_w, ca_qkv_b);
        kF23     <<<1024, 256, 67584>>>();
        kF3b     <<<32, 256>>>(ca_temp);
        kF4_out  <<<1024, 256, 76800>>>(ca_proj_w, ca_proj_b, out);
    } else {
        kA_win   <<<1024, 256, 66560>>>(x, wqkv_w, wqkv_b);
        kB_bra   <<<1024, 256, 66560>>>(x, bqkv_w, bqkv_b);
        kC_route <<<1024, 256>>>();
        kD_attn  <<<2048, 128, 49152>>>();
        kE_lepe  <<<1024, 256, 57344>>>(lepe_w, lepe_b);
        kF1_caqkv<<<1024, 256, 100352>>>(ca_qkv_w, ca_qkv_b);
        kF23     <<<1024, 256, 67584>>>();
        kF3b     <<<32, 256>>>(ca_temp);
        kF4_out  <<<1024, 256, 76800>>>(ca_proj_w, ca_proj_b, out);
    }
}

// round 17
// speedup vs baseline: 1.0596x; 1.0062x over previous
#include <cuda_runtime.h>
#include <cuda_fp16.h>
#include <math.h>

#define BB   4
#define LL   16384
#define SCALE 0.08838834764831845f   // 128^-0.5

typedef unsigned long long ull;
typedef ulonglong2 ull2;

__device__ __forceinline__ ull pk2(float a, float b) {
    ull r; asm("mov.b64 %0,{%1,%2};" : "=l"(r) : "f"(a), "f"(b)); return r;
}
__device__ __forceinline__ ull dup2(float a) { return pk2(a, a); }
__device__ __forceinline__ void up2(ull v, float& a, float& b) {
    asm("mov.b64 {%0,%1},%2;" : "=f"(a), "=f"(b) : "l"(v));
}
__device__ __forceinline__ ull fma2(ull a, ull b, ull c) {
    ull d; asm("fma.rn.f32x2 %0,%1,%2,%3;" : "=l"(d) : "l"(a), "l"(b), "l"(c)); return d;
}
__device__ __forceinline__ ull mul2(ull a, ull b) {
    ull d; asm("mul.rn.f32x2 %0,%1,%2;" : "=l"(d) : "l"(a), "l"(b)); return d;
}
__device__ __forceinline__ ull add2(ull a, ull b) {
    ull d; asm("add.rn.f32x2 %0,%1,%2;" : "=l"(d) : "l"(a), "l"(b)); return d;
}
__device__ __forceinline__ float hadd2(ull v) { float a, b; up2(v, a, b); return a + b; }

// ---------------- scratch ----------------------------------------------------
__device__ __align__(16) float  g_winv[BB*256*64*64];   // (b,r,t,c) window V
__device__ __align__(16) float  g_vtok[BB*256*64*64];   // (b,r,t,c) bra V token-major
__device__ __align__(16) float  g_qb  [BB*8*256*64*8];  // (b,h,r,t,d) PRE-SCALED
__device__ __align__(16) __half g_kh  [BB*8*256*64*8];  // (b,h,r,t,d) fp16 k
__device__ __align__(16) float  g_vb  [BB*8*256*64*8];
__device__ __align__(16) float  g_qr  [BB*256*64];
__device__ __align__(16) float  g_krT [BB*64*256];      // channel-major pooled k
__device__ int   g_idx [BB*256*4];
__device__ __align__(16) float g_mid [(size_t)BB*LL*128];   // attention outputs
__device__ __align__(16) float g_lepe[(size_t)BB*LL*128];   // lepe (added in kF1)
__device__ __align__(16) float g_cq  [(size_t)BB*LL*128];   // token-major
__device__ __align__(16) float g_ck  [(size_t)BB*LL*128];
__device__ __align__(16) float g_cv  [(size_t)BB*LL*128];
__device__ float g_norm2[2*BB*128];
__device__ float g_gram[32*256];
__device__ float g_attn[32*256];

// ---------------- kA: window QKV GEMM + window attention --------------------
__global__ void kA_win(const float* __restrict__ x, const float* __restrict__ w,
                       const float* __restrict__ bias) {
    extern __shared__ float sm[];
    float* s_xT  = sm;            // 64 k x 68 m
    float* s_w   = sm + 64*68;    // 64 x 192 (reused as s_qkv)
    float* s_qkv = s_w;
    int wid = blockIdx.x;
    int b = wid >> 8, r = wid & 255, ry = r >> 4, rx = r & 15;
    int tid = threadIdx.x;

    for (int i = tid; i < 4096; i += 256) {
        int t = i >> 6, c = i & 63;
        int y = ry*8 + (t >> 3), xx = rx*8 + (t & 7);
        s_xT[c*68 + t] = x[(((size_t)b*128 + y)*128 + xx)*128 + c];
    }
    for (int i = tid; i < 12288; i += 256) s_w[i] = w[i];
    __syncthreads();

    int t_m = tid & 15, t_n = tid >> 4;     // m = t_m*4, n = t_n*12
    ull acc[4][6];
    #pragma unroll
    for (int i = 0; i < 4; i++)
        #pragma unroll
        for (int j = 0; j < 6; j++) acc[i][j] = 0ull;
    for (int k = 0; k < 64; k++) {
        float4 a4 = *(const float4*)(s_xT + k*68 + t_m*4);
        ull a0 = dup2(a4.x), a1 = dup2(a4.y), a2 = dup2(a4.z), a3 = dup2(a4.w);
        const ull2* bp = (const ull2*)(s_w + k*192 + t_n*12);
        ull2 B0 = bp[0], B1 = bp[1], B2 = bp[2];
        ull b0=B0.x, b1=B0.y, b2=B1.x, b3=B1.y, b4=B2.x, b5=B2.y;
        acc[0][0]=fma2(a0,b0,acc[0][0]); acc[0][1]=fma2(a0,b1,acc[0][1]);
        acc[0][2]=fma2(a0,b2,acc[0][2]); acc[0][3]=fma2(a0,b3,acc[0][3]);
        acc[0][4]=fma2(a0,b4,acc[0][4]); acc[0][5]=fma2(a0,b5,acc[0][5]);
        acc[1][0]=fma2(a1,b0,acc[1][0]); acc[1][1]=fma2(a1,b1,acc[1][1]);
        acc[1][2]=fma2(a1,b2,acc[1][2]); acc[1][3]=fma2(a1,b3,acc[1][3]);
        acc[1][4]=fma2(a1,b4,acc[1][4]); acc[1][5]=fma2(a1,b5,acc[1][5]);
        acc[2][0]=fma2(a2,b0,acc[2][0]); acc[2][1]=fma2(a2,b1,acc[2][1]);
        acc[2][2]=fma2(a2,b2,acc[2][2]); acc[2][3]=fma2(a2,b3,acc[2][3]);
        acc[2][4]=fma2(a2,b4,acc[2][4]); acc[2][5]=fma2(a2,b5,acc[2][5]);
        acc[3][0]=fma2(a3,b0,acc[3][0]); acc[3][1]=fma2(a3,b1,acc[3][1]);
        acc[3][2]=fma2(a3,b2,acc[3][2]); acc[3][3]=fma2(a3,b3,acc[3][3]);
        acc[3][4]=fma2(a3,b4,acc[3][4]); acc[3][5]=fma2(a3,b5,acc[3][5]);
    }
    __syncthreads();
    {
        float bb[12];
        #pragma unroll
        for (int j = 0; j < 12; j++) bb[j] = __ldg(bias + t_n*12 + j);
        #pragma unroll
        for (int i = 0; i < 4; i++)
            #pragma unroll
            for (int j = 0; j < 6; j++) {
                float lo, hi; up2(acc[i][j], lo, hi);
                s_qkv[(t_m*4+i)*192 + t_n*12 + 2*j]     = lo + bb[2*j];
                s_qkv[(t_m*4+i)*192 + t_n*12 + 2*j + 1] = hi + bb[2*j+1];
            }
    }
    __syncthreads();

    size_t base = (size_t)wid * 4096;
    for (int i = tid; i < 4096; i += 256) {
        int t = i >> 6, c = i & 63;
        g_winv[base + i] = s_qkv[t*192 + 128 + c];
    }

    // attention: warp = head, 2 q-rows per thread
    int h = tid >> 5, lane = tid & 31;
    ull sc = dup2(SCALE);
    const ull2* qp0 = (const ull2*)(s_qkv + lane*192 + h*8);
    const ull2* qp1 = (const ull2*)(s_qkv + (lane+32)*192 + h*8);
    ull2 Q0a = qp0[0], Q0b = qp0[1], Q1a = qp1[0], Q1b = qp1[1];
    ull q0[4] = {mul2(Q0a.x,sc), mul2(Q0a.y,sc), mul2(Q0b.x,sc), mul2(Q0b.y,sc)};
    ull q1[4] = {mul2(Q1a.x,sc), mul2(Q1a.y,sc), mul2(Q1b.x,sc), mul2(Q1b.y,sc)};
    float ssum0 = 0.f, ssum1 = 0.f;
    ull a0[4] = {0,0,0,0}, a1[4] = {0,0,0,0};
    #pragma unroll 2
    for (int j = 0; j < 64; j++) {
        const ull2* kp = (const ull2*)(s_qkv + j*192 + 64 + h*8);
        ull2 K0 = kp[0], K1 = kp[1];
        ull s20 = fma2(q0[0],K0.x, fma2(q0[1],K0.y, fma2(q0[2],K1.x, mul2(q0[3],K1.y))));
        ull s21 = fma2(q1[0],K0.x, fma2(q1[1],K0.y, fma2(q1[2],K1.x, mul2(q1[3],K1.y))));
        float e0 = __expf(hadd2(s20));
        float e1 = __expf(hadd2(s21));
        ssum0 += e0; ssum1 += e1;
        ull e0d = dup2(e0), e1d = dup2(e1);
        const ull2* vp = (const ull2*)(s_qkv + j*192 + 128 + h*8);
        ull2 V0 = vp[0], V1 = vp[1];
        a0[0]=fma2(e0d,V0.x,a0[0]); a0[1]=fma2(e0d,V0.y,a0[1]);
        a0[2]=fma2(e0d,V1.x,a0[2]); a0[3]=fma2(e0d,V1.y,a0[3]);
        a1[0]=fma2(e1d,V0.x,a1[0]); a1[1]=fma2(e1d,V0.y,a1[1]);
        a1[2]=fma2(e1d,V1.x,a1[2]); a1[3]=fma2(e1d,V1.y,a1[3]);
    }
    ull i0 = dup2(1.f/ssum0), i1 = dup2(1.f/ssum1);
    {
        int row = lane;
        int y = ry*8 + (row>>3), xx = rx*8 + (row&7);
        ull* mo = (ull*)(g_mid + ((size_t)b*LL + y*128 + xx)*128 + h*8);
        mo[0]=mul2(a0[0],i0); mo[1]=mul2(a0[1],i0); mo[2]=mul2(a0[2],i0); mo[3]=mul2(a0[3],i0);
        row = lane + 32;
        y = ry*8 + (row>>3); xx = rx*8 + (row&7);
        mo = (ull*)(g_mid + ((size_t)b*LL + y*128 + xx)*128 + h*8);
        mo[0]=mul2(a1[0],i1); mo[1]=mul2(a1[1],i1); mo[2]=mul2(a1[2],i1); mo[3]=mul2(a1[3],i1);
    }
}

// ---------------- kB: BRA QKV GEMM (head-major q/kh/v + token-major V) ------
__global__ void kB_bra(const float* __restrict__ x, const float* __restrict__ w,
                       const float* __restrict__ bias) {
    extern __shared__ float sm[];
    float* s_xT  = sm;
    float* s_w   = sm + 64*68;
    float* s_qkv = s_w;
    int wid = blockIdx.x;
    int b = wid >> 8, r = wid & 255, ry = r >> 4, rx = r & 15;
    int tid = threadIdx.x;

    for (int i = tid; i < 4096; i += 256) {
        int t = i >> 6, c = i & 63;
        int y = ry*8 + (t >> 3), xx = rx*8 + (t & 7);
        s_xT[c*68 + t] = x[(((size_t)b*128 + y)*128 + xx)*128 + 64 + c];
    }
    for (int i = tid; i < 12288; i += 256) s_w[i] = w[i];
    __syncthreads();

    int t_m = tid & 15, t_n = tid >> 4;
    ull acc[4][6];
    #pragma unroll
    for (int i = 0; i < 4; i++)
        #pragma unroll
        for (int j = 0; j < 6; j++) acc[i][j] = 0ull;
    for (int k = 0; k < 64; k++) {
        float4 a4 = *(const float4*)(s_xT + k*68 + t_m*4);
        ull a0 = dup2(a4.x), a1 = dup2(a4.y), a2 = dup2(a4.z), a3 = dup2(a4.w);
        const ull2* bp = (const ull2*)(s_w + k*192 + t_n*12);
        ull2 B0 = bp[0], B1 = bp[1], B2 = bp[2];
        ull b0=B0.x, b1=B0.y, b2=B1.x, b3=B1.y, b4=B2.x, b5=B2.y;
        acc[0][0]=fma2(a0,b0,acc[0][0]); acc[0][1]=fma2(a0,b1,acc[0][1]);
        acc[0][2]=fma2(a0,b2,acc[0][2]); acc[0][3]=fma2(a0,b3,acc[0][3]);
        acc[0][4]=fma2(a0,b4,acc[0][4]); acc[0][5]=fma2(a0,b5,acc[0][5]);
        acc[1][0]=fma2(a1,b0,acc[1][0]); acc[1][1]=fma2(a1,b1,acc[1][1]);
        acc[1][2]=fma2(a1,b2,acc[1][2]); acc[1][3]=fma2(a1,b3,acc[1][3]);
        acc[1][4]=fma2(a1,b4,acc[1][4]); acc[1][5]=fma2(a1,b5,acc[1][5]);
        acc[2][0]=fma2(a2,b0,acc[2][0]); acc[2][1]=fma2(a2,b1,acc[2][1]);
        acc[2][2]=fma2(a2,b2,acc[2][2]); acc[2][3]=fma2(a2,b3,acc[2][3]);
        acc[2][4]=fma2(a2,b4,acc[2][4]); acc[2][5]=fma2(a2,b5,acc[2][5]);
        acc[3][0]=fma2(a3,b0,acc[3][0]); acc[3][1]=fma2(a3,b1,acc[3][1]);
        acc[3][2]=fma2(a3,b2,acc[3][2]); acc[3][3]=fma2(a3,b3,acc[3][3]);
        acc[3][4]=fma2(a3,b4,acc[3][4]); acc[3][5]=fma2(a3,b5,acc[3][5]);
    }
    __syncthreads();
    {
        float bb[12];
        #pragma unroll
        for (int j = 0; j < 12; j++) bb[j] = __ldg(bias + t_n*12 + j);
        #pragma unroll
        for (int i = 0; i < 4; i++)
            #pragma unroll
            for (int j = 0; j < 6; j++) {
                float lo, hi; up2(acc[i][j], lo, hi);
                s_qkv[(t_m*4+i)*192 + t_n*12 + 2*j]     = lo + bb[2*j];
                s_qkv[(t_m*4+i)*192 + t_n*12 + 2*j + 1] = hi + bb[2*j+1];
            }
    }
    __syncthreads();

    for (int i = tid; i < 4096; i += 256) {
        int hh = i >> 9, rest = i & 511;
        int t = rest >> 3, d = rest & 7;
        size_t off = ((size_t)(b*8 + hh)*256 + r)*512 + rest;
        g_qb[off] = s_qkv[t*192 + hh*8 + d] * SCALE;            // pre-scaled
        g_kh[off] = __float2half(s_qkv[t*192 + 64 + hh*8 + d]); // fp16 k
        g_vb[off] = s_qkv[t*192 + 128 + hh*8 + d];
    }
    size_t base = (size_t)wid * 4096;
    for (int i = tid; i < 4096; i += 256) {
        int t = i >> 6, c = i & 63;
        g_vtok[base + i] = s_qkv[t*192 + 128 + c];
    }
    if (tid < 64) {
        float sq = 0.f, sk = 0.f;
        for (int t = 0; t < 64; t++) {
            sq += s_qkv[t*192 + tid];
            sk += s_qkv[t*192 + 64 + tid];
        }
        g_qr[wid*64 + tid] = sq * 0.015625f;
        g_krT[((size_t)b*64 + tid)*256 + r] = sk * 0.015625f;
    }
}

// ---------------- kC: routing (coalesced) + warp-register top-4 + zeroing ---
__global__ void kC_route() {
    __shared__ float s_q[64];
    __shared__ float s_a[256];
    int bx = blockIdx.x;
    int b = bx >> 8, i = bx & 255;
    int tid = threadIdx.x;
    if (bx < 32) g_gram[bx*256 + tid] = 0.f;
    else if (bx < 36) g_norm2[(bx-32)*256 + tid] = 0.f;
    if (tid < 64) s_q[tid] = g_qr[(b*256 + i)*64 + tid];
    __syncthreads();
    const float* krT = g_krT + (size_t)b*64*256 + tid;   // lane-coalesced
    float a = 0.f;
    #pragma unroll 8
    for (int c = 0; c < 64; c++) a += s_q[c]*krT[c*256];
    s_a[tid] = a;
    __syncthreads();
    if (tid < 32) {
        float v[8];
        #pragma unroll
        for (int j = 0; j < 8; j++) v[j] = s_a[tid + j*32];
        #pragma unroll
        for (int s = 0; s < 4; s++) {
            float bv = v[0]; int bj = 0;
            #pragma unroll
            for (int j = 1; j < 8; j++)
                if (v[j] > bv) { bv = v[j]; bj = j; }
            int bidx = tid + bj*32;
            #pragma unroll
            for (int off = 16; off > 0; off >>= 1) {
                float ov = __shfl_down_sync(0xffffffffu, bv, off);
                int   oi = __shfl_down_sync(0xffffffffu, bidx, off);
                if (ov > bv || (ov == bv && oi < bidx)) { bv = ov; bidx = oi; }
            }
            bidx = __shfl_sync(0xffffffffu, bidx, 0);
            if (tid == 0) g_idx[(b*256 + i)*4 + s] = bidx;
            if ((bidx & 31) == tid) v[bidx >> 5] = -INFINITY;
        }
    }
}

// ---------------- kD: BRA attn (4 heads/block, key-split, 256 thr) ----------
__global__ void kD_attn() {
    extern __shared__ char smd[];
    __half* s_k   = (__half*)smd;            // 4*256*8 halfs = 16KB
    float*  s_v   = (float*)(smd + 16384);   // 4*256*8 floats = 32KB
    float*  s_red = (float*)smd;             // overlays s_k after main loop
    __shared__ int s_i4[4];
    int bid = blockIdx.x;                    // 2048: b(4) x hp(2) x r(256)
    int b = bid >> 9, hp = (bid >> 8) & 1, r = bid & 255;
    int tid = threadIdx.x;                   // 256
    if (tid < 4) s_i4[tid] = g_idx[(b*256 + r)*4 + tid];
    __syncthreads();
    for (int i = tid; i < 1024; i += 256) {  // k: 16B per key
        int hl = i >> 8, key = i & 255;
        int reg = s_i4[key >> 6], t = key & 63;
        size_t off = ((size_t)(b*8 + hp*4 + hl)*256 + reg)*512 + t*8;
        *(uint4*)(s_k + (size_t)i*8) = *(const uint4*)(g_kh + off);
    }
    for (int i = tid; i < 2048; i += 256) {  // v: 2x16B per key
        int hl = i >> 9, rem = i & 511;
        int key = rem >> 1, d4 = rem & 1;
        int reg = s_i4[key >> 6], t = key & 63;
        size_t off = ((size_t)(b*8 + hp*4 + hl)*256 + reg)*512 + t*8 + d4*4;
        *(float4*)(s_v + (size_t)i*4) = *(const float4*)(g_vb + off);
    }
    __syncthreads();
    int khalf = tid >> 7;                    // 0: keys 0..127, 1: keys 128..255
    int t128 = tid & 127;
    int hl = t128 >> 5, lane = t128 & 31;    // warp-in-half = head
    int h = hp*4 + hl;
    size_t qbase = ((size_t)(b*8 + h)*256 + r)*512;
    const float2* qa = (const float2*)(g_qb + qbase + lane*8);       // pre-scaled
    const float2* qb2 = (const float2*)(g_qb + qbase + (lane+32)*8);
    __half2 qh0[4], qh1[4];
    #pragma unroll
    for (int d = 0; d < 4; d++) {
        qh0[d] = __float22half2_rn(qa[d]);
        qh1[d] = __float22half2_rn(qb2[d]);
    }
    const uint4* kp = (const uint4*)(s_k + (size_t)hl*2048) + khalf*128;
    const ull2*  vp = (const ull2*)(s_v + (size_t)hl*2048) + khalf*256;
    float ss0 = 0.f, ss1 = 0.f;
    ull a00=0,a01=0,a02=0,a03=0, a10=0,a11=0,a12=0,a13=0;
    #pragma unroll 2
    for (int j = 0; j < 128; j++) {
        uint4 kk = kp[j];
        __half2 k0 = *(__half2*)&kk.x, k1 = *(__half2*)&kk.y,
                k2 = *(__half2*)&kk.z, k3 = *(__half2*)&kk.w;
        __half2 h0 = __hfma2(qh0[1], k1, __hmul2(qh0[0], k0));
        h0 = __hfma2(qh0[3], k3, __hfma2(qh0[2], k2, h0));
        __half2 h1 = __hfma2(qh1[1], k1, __hmul2(qh1[0], k0));
        h1 = __hfma2(qh1[3], k3, __hfma2(qh1[2], k2, h1));
        float2 f0 = __half22float2(h0);
        float2 f1 = __half22float2(h1);
        float e0 = __expf(f0.x + f0.y);
        float e1 = __expf(f1.x + f1.y);
        ss0 += e0; ss1 += e1;
        ull e0d = dup2(e0), e1d = dup2(e1);
        ull2 V0 = vp[j*2], V1 = vp[j*2 + 1];
        a00 = fma2(e0d, V0.x, a00); a01 = fma2(e0d, V0.y, a01);
        a02 = fma2(e0d, V1.x, a02); a03 = fma2(e0d, V1.y, a03);
        a10 = fma2(e1d, V0.x, a10); a11 = fma2(e1d, V0.y, a11);
        a12 = fma2(e1d, V1.x, a12); a13 = fma2(e1d, V1.y, a13);
    }
    __syncthreads();   // all reads of s_k done; s_red may overwrite it
    if (khalf == 1) {
        float* dst = s_red + t128*18;
        dst[0] = ss0; dst[1] = ss1;
        ull* d8 = (ull*)(dst + 2);
        d8[0]=a00; d8[1]=a01; d8[2]=a02; d8[3]=a03;
        d8[4]=a10; d8[5]=a11; d8[6]=a12; d8[7]=a13;
    }
    __syncthreads();
    if (khalf == 0) {
        const float* src = s_red + t128*18;
        ss0 += src[0]; ss1 += src[1];
        const ull* s8 = (const ull*)(src + 2);
        a00 = add2(a00, s8[0]); a01 = add2(a01, s8[1]);
        a02 = add2(a02, s8[2]); a03 = add2(a03, s8[3]);
        a10 = add2(a10, s8[4]); a11 = add2(a11, s8[5]);
        a12 = add2(a12, s8[6]); a13 = add2(a13, s8[7]);
        ull i0 = dup2(1.f/ss0), i1 = dup2(1.f/ss1);
        int row = lane;
        int y = (r >> 4)*8 + (row >> 3), xx = (r & 15)*8 + (row & 7);
        ull* mo = (ull*)(g_mid + ((size_t)b*LL + y*128 + xx)*128 + 64 + h*8);
        mo[0]=mul2(a00,i0); mo[1]=mul2(a01,i0); mo[2]=mul2(a02,i0); mo[3]=mul2(a03,i0);
        row = lane + 32;
        y = (r >> 4)*8 + (row >> 3); xx = (r & 15)*8 + (row & 7);
        mo = (ull*)(g_mid + ((size_t)b*LL + y*128 + xx)*128 + 64 + h*8);
        mo[0]=mul2(a10,i1); mo[1]=mul2(a11,i1); mo[2]=mul2(a12,i1); mo[3]=mul2(a13,i1);
    }
}

// ---------------- kE: depthwise 3x3 LEPE, smem-tiled (writes g_lepe) --------
__global__ void kE_lepe(const float* __restrict__ lw, const float* __restrict__ lb) {
    extern __shared__ float se[];
    float* s_v  = se;             // vtok patch: 100 pos x 64 ch = 6400
    float* s_wi = se + 6400;      // winv patch: 6400
    float* s_lw = se + 12800;     // 128*9 = 1152
    float* s_lb = se + 13952;     // 128
    int bid = blockIdx.x;         // 1024 = b(4) x r(256)
    int b = bid >> 8, r = bid & 255, ry = r >> 4, rx = r & 15;
    int tid = threadIdx.x;        // 256

    for (int i = tid; i < 1152; i += 256) s_lw[i] = lw[i];
    if (tid < 128) s_lb[tid] = lb[tid];
    for (int i = tid; i < 3200; i += 256) {   // 2 arrays x 100 pos x 16 float4
        int half = i >= 1600;
        int rem = half ? i - 1600 : i;
        int pos = rem >> 4, f4 = rem & 15;
        int py = pos / 10, px = pos - py*10;
        int y = ry*8 - 1 + py, x = rx*8 - 1 + px;
        float4 val = make_float4(0.f, 0.f, 0.f, 0.f);
        if (y >= 0 && y < 128 && x >= 0 && x < 128) {
            int rr = (y >> 3)*16 + (x >> 3), tt = (y & 7)*8 + (x & 7);
            const float* src = half ? g_winv : g_vtok;
            val = *(const float4*)(src + ((size_t)(b*256 + rr))*4096 + tt*64 + f4*4);
        }
        float* dst = half ? s_wi : s_v;
        *(float4*)(dst + pos*64 + f4*4) = val;
    }
    __syncthreads();

    for (int i = tid; i < 8192; i += 256) {   // 64 tokens x 128 ch
        int tok = i >> 7, c = i & 127;
        int iy = tok >> 3, ix = tok & 7;
        const float* s_src = (c < 64) ? s_v : s_wi;
        int cc = c & 63;
        float acc = s_lb[c];
        const float* wr = s_lw + c*9;
        #pragma unroll
        for (int ky = 0; ky < 3; ky++)
            #pragma unroll
            for (int kx = 0; kx < 3; kx++)
                acc += s_src[((iy+ky)*10 + (ix+kx))*64 + cc] * wr[ky*3 + kx];
        int y = ry*8 + iy, x = rx*8 + ix;
        g_lepe[((size_t)b*LL + y*128 + x)*128 + c] = acc;
    }
}

// ---------------- kF1: CA-qkv GEMM, A = g_mid + g_lepe, single launch -------
__global__ void kF1_caqkv(const float* __restrict__ w, const float* __restrict__ bias) {
    extern __shared__ float sm[];
    float* AsT = sm;          // [128 k][68 m]
    float* Bs  = sm + 8704;   // [128 k][128 n] (reused as Cs)
    float* Cs  = Bs;
    int m0 = blockIdx.x * 64;
    int tid = threadIdx.x;

    for (int i = tid; i < 8192; i += 256) {
        int t = i >> 7, k = i & 127;
        size_t go = (size_t)(m0 + t)*128 + k;
        AsT[k*68 + t] = g_mid[go] + g_lepe[go];
    }

    int t_m = tid & 15, t_n = tid >> 4;
    for (int nb = 0; nb < 3; nb++) {
        __syncthreads();
        for (int i = tid; i < 16384; i += 256) {
            int k = i >> 7, n = i & 127;
            Bs[i] = w[k*384 + nb*128 + n];
        }
        __syncthreads();

        ull acc[4][4];
        #pragma unroll
        for (int i = 0; i < 4; i++)
            #pragma unroll
            for (int j = 0; j < 4; j++) acc[i][j] = 0ull;
        #pragma unroll 4
        for (int k = 0; k < 128; k++) {
            float4 a4 = *(const float4*)(AsT + k*68 + t_m*4);
            ull a0 = dup2(a4.x), a1 = dup2(a4.y), a2 = dup2(a4.z), a3 = dup2(a4.w);
            const ull2* bp = (const ull2*)(Bs + k*128 + t_n*8);
            ull2 B0 = bp[0], B1 = bp[1];
            ull b0=B0.x, b1=B0.y, b2=B1.x, b3=B1.y;
            acc[0][0]=fma2(a0,b0,acc[0][0]); acc[0][1]=fma2(a0,b1,acc[0][1]);
            acc[0][2]=fma2(a0,b2,acc[0][2]); acc[0][3]=fma2(a0,b3,acc[0][3]);
            acc[1][0]=fma2(a1,b0,acc[1][0]); acc[1][1]=fma2(a1,b1,acc[1][1]);
            acc[1][2]=fma2(a1,b2,acc[1][2]); acc[1][3]=fma2(a1,b3,acc[1][3]);
            acc[2][0]=fma2(a2,b0,acc[2][0]); acc[2][1]=fma2(a2,b1,acc[2][1]);
            acc[2][2]=fma2(a2,b2,acc[2][2]); acc[2][3]=fma2(a2,b3,acc[2][3]);
            acc[3][0]=fma2(a3,b0,acc[3][0]); acc[3][1]=fma2(a3,b1,acc[3][1]);
            acc[3][2]=fma2(a3,b2,acc[3][2]); acc[3][3]=fma2(a3,b3,acc[3][3]);
        }
        __syncthreads();

        {
            float bb[8];
            #pragma unroll
            for (int j = 0; j < 8; j++) bb[j] = __ldg(bias + nb*128 + t_n*8 + j);
            #pragma unroll
            for (int i = 0; i < 4; i++)
                #pragma unroll
                for (int j = 0; j < 4; j++) {
                    float lo, hi; up2(acc[i][j], lo, hi);
                    Cs[(t_m*4+i)*132 + t_n*8 + 2*j]     = lo + bb[2*j];
                    Cs[(t_m*4+i)*132 + t_n*8 + 2*j + 1] = hi + bb[2*j+1];
                }
        }
        __syncthreads();
        float* dst = (nb == 0) ? g_cq : (nb == 1) ? g_ck : g_cv;
        for (int i = tid; i < 2048; i += 256) {
            int m = i >> 5, nf = i & 31;
            *(float4*)(dst + (size_t)(m0 + m)*128 + nf*4) = *(const float4*)(Cs + m*132 + nf*4);
        }
    }
}

// ---------------- kF23: norms + grams, channel-major tiles (pad 66) ---------
__global__ void kF23() {
    extern __shared__ float sm[];
    float* qs = sm;            // 128 ch x 66 t
    float* ks = sm + 8448;
    int bid = blockIdx.x;      // 1024 = b(4) x chunk(256)
    int b = bid >> 8, ch = bid & 255;
    int l0 = ch*64;
    int tid = threadIdx.x;
    const float4* qsrc = (const float4*)(g_cq + ((size_t)b*LL + l0)*128);
    const float4* ksrc = (const float4*)(g_ck + ((size_t)b*LL + l0)*128);
    for (int i = tid; i < 2048; i += 256) {
        int t = i >> 5, nf = i & 31;
        float4 q4 = qsrc[t*32 + nf];
        float4 k4 = ksrc[t*32 + nf];
        int c = nf*4;
        qs[(c+0)*66 + t] = q4.x; qs[(c+1)*66 + t] = q4.y;
        qs[(c+2)*66 + t] = q4.z; qs[(c+3)*66 + t] = q4.w;
        ks[(c+0)*66 + t] = k4.x; ks[(c+1)*66 + t] = k4.y;
        ks[(c+2)*66 + t] = k4.z; ks[(c+3)*66 + t] = k4.w;
    }
    __syncthreads();
    {
        const ull* bp = (tid < 128) ? (const ull*)(qs + tid*66)
                                    : (const ull*)(ks + (tid - 128)*66);
        ull acc2 = 0ull;
        #pragma unroll 8
        for (int t2 = 0; t2 < 32; t2++) { ull v = bp[t2]; acc2 = fma2(v, v, acc2); }
        atomicAdd(&g_norm2[((tid < 128) ? 0 : 512) + b*128 + (tid & 127)], hadd2(acc2));
    }
    int d = tid >> 4, e = tid & 15;
    #pragma unroll
    for (int h = 0; h < 8; h++) {
        const ull* qp2 = (const ull*)(qs + (h*16 + d)*66);
        const ull* kp2 = (const ull*)(ks + (h*16 + e)*66);
        ull acc2 = 0ull;
        #pragma unroll 8
        for (int t2 = 0; t2 < 32; t2++) acc2 = fma2(qp2[t2], kp2[t2], acc2);
        atomicAdd(&g_gram[(b*8 + h)*256 + tid], hadd2(acc2));
    }
}

// ---------------- kF3b: normalize + softmax ----------------------------------
__global__ void kF3b(const float* __restrict__ temp) {
    __shared__ float smm[256];
    int bh = blockIdx.x;
    int b = bh >> 3, h = bh & 7;
    int tid = threadIdx.x;
    int d = tid >> 4, e = tid & 15;
    int rowq = b*128 + h*16;
    float nq = fmaxf(sqrtf(g_norm2[rowq + d]), 1e-12f);
    float nk = fmaxf(sqrtf(g_norm2[512 + rowq + e]), 1e-12f);
    smm[tid] = g_gram[bh*256 + tid] / (nq*nk) * __ldg(temp + h);
    __syncthreads();
    if (tid < 16) {
        float mx = -INFINITY;
        for (int j = 0; j < 16; j++) mx = fmaxf(mx, smm[tid*16 + j]);
        float ssum = 0.f, ex[16];
        for (int j = 0; j < 16; j++) { ex[j] = __expf(smm[tid*16 + j] - mx); ssum += ex[j]; }
        float inv = 1.f/ssum;
        for (int j = 0; j < 16; j++) g_attn[bh*256 + tid*16 + j] = ex[j]*inv;
    }
}

// ---------------- kF4: cout mix (attn pad 18) + 128x128 projection ----------
__global__ void kF4_out(const float* __restrict__ pw, const float* __restrict__ pb,
                        float* __restrict__ out) {
    extern __shared__ float sm[];
    float* s_attn = sm;           // 128 ch x 18
    float* s_cv   = sm + 2304;    // 64 x 128
    float* coutT  = sm + 10496;   // 128 k x 68 m
    int tok0 = blockIdx.x * 64;
    int b = tok0 >> 14;
    int tid = threadIdx.x;
    for (int i = tid; i < 2048; i += 256)
        s_attn[(i >> 4)*18 + (i & 15)] = g_attn[b*2048 + i];
    for (int i = tid; i < 8192; i += 256) s_cv[i] = g_cv[(size_t)tok0*128 + i];
    __syncthreads();
    for (int i = tid; i < 8192; i += 256) {
        int m = i >> 7, chn = i & 127;
        int h = chn >> 4;
        const ull* ap  = (const ull*)(s_attn + chn*18);
        const ull2* cvp = (const ull2*)(s_cv + m*128 + h*16);
        ull2 C0 = cvp[0], C1 = cvp[1], C2 = cvp[2], C3 = cvp[3];
        ull acc = mul2(ap[0], C0.x);
        acc = fma2(ap[1], C0.y, acc);
        acc = fma2(ap[2], C1.x, acc);
        acc = fma2(ap[3], C1.y, acc);
        acc = fma2(ap[4], C2.x, acc);
        acc = fma2(ap[5], C2.y, acc);
        acc = fma2(ap[6], C3.x, acc);
        acc = fma2(ap[7], C3.y, acc);
        coutT[chn*68 + m] = hadd2(acc);
    }
    __syncthreads();
    int t_m = tid & 15, t_n = tid >> 4;
    ull acc[4][4];
    #pragma unroll
    for (int i = 0; i < 4; i++)
        #pragma unroll
        for (int j = 0; j < 4; j++) acc[i][j] = 0ull;
    #pragma unroll 4
    for (int k = 0; k < 128; k++) {
        float4 a4 = *(const float4*)(coutT + k*68 + t_m*4);
        ull a0 = dup2(a4.x), a1 = dup2(a4.y), a2 = dup2(a4.z), a3 = dup2(a4.w);
        float4 w0 = __ldg((const float4*)(pw + k*128 + t_n*8));
        float4 w1 = __ldg((const float4*)(pw + k*128 + t_n*8 + 4));
        ull b0 = pk2(w0.x, w0.y), b1 = pk2(w0.z, w0.w);
        ull b2 = pk2(w1.x, w1.y), b3 = pk2(w1.z, w1.w);
        acc[0][0]=fma2(a0,b0,acc[0][0]); acc[0][1]=fma2(a0,b1,acc[0][1]);
        acc[0][2]=fma2(a0,b2,acc[0][2]); acc[0][3]=fma2(a0,b3,acc[0][3]);
        acc[1][0]=fma2(a1,b0,acc[1][0]); acc[1][1]=fma2(a1,b1,acc[1][1]);
        acc[1][2]=fma2(a1,b2,acc[1][2]); acc[1][3]=fma2(a1,b3,acc[1][3]);
        acc[2][0]=fma2(a2,b0,acc[2][0]); acc[2][1]=fma2(a2,b1,acc[2][1]);
        acc[2][2]=fma2(a2,b2,acc[2][2]); acc[2][3]=fma2(a2,b3,acc[2][3]);
        acc[3][0]=fma2(a3,b0,acc[3][0]); acc[3][1]=fma2(a3,b1,acc[3][1]);
        acc[3][2]=fma2(a3,b2,acc[3][2]); acc[3][3]=fma2(a3,b3,acc[3][3]);
    }
    float4 pb0 = __ldg((const float4*)(pb + t_n*8));
    float4 pb1 = __ldg((const float4*)(pb + t_n*8 + 4));
    float bb[8] = {pb0.x,pb0.y,pb0.z,pb0.w,pb1.x,pb1.y,pb1.z,pb1.w};
    #pragma unroll
    for (int i = 0; i < 4; i++) {
        float r[8];
        #pragma unroll
        for (int j = 0; j < 4; j++) {
            float lo, hi; up2(acc[i][j], lo, hi);
            r[2*j] = lo + bb[2*j]; r[2*j+1] = hi + bb[2*j+1];
        }
        float* op = out + ((size_t)tok0 + t_m*4 + i)*128 + t_n*8;
        *(float4*)op     = make_float4(r[0], r[1], r[2], r[3]);
        *(float4*)(op+4) = make_float4(r[4], r[5], r[6], r[7]);
    }
}

// ---------------- streams/events (module init, reused every capture) ---------
struct LaunchRes {
    cudaStream_t s1 = 0, s2 = 0;
    cudaEvent_t evRoot = 0, evA = 0, evB = 0, evE = 0;
    bool ok = false;
    LaunchRes() {
        cudaFuncSetAttribute(kA_win,   cudaFuncAttributeMaxDynamicSharedMemorySize, 66560);
        cudaFuncSetAttribute(kB_bra,   cudaFuncAttributeMaxDynamicSharedMemorySize, 66560);
        cudaFuncSetAttribute(kD_attn,  cudaFuncAttributeMaxDynamicSharedMemorySize, 49152);
        cudaFuncSetAttribute(kE_lepe,  cudaFuncAttributeMaxDynamicSharedMemorySize, 57344);
        cudaFuncSetAttribute(kF1_caqkv,cudaFuncAttributeMaxDynamicSharedMemorySize, 100352);
        cudaFuncSetAttribute(kF23,     cudaFuncAttributeMaxDynamicSharedMemorySize, 67584);
        cudaFuncSetAttribute(kF4_out,  cudaFuncAttributeMaxDynamicSharedMemorySize, 76800);
        bool good = true;
        good &= cudaStreamCreateWithFlags(&s1, cudaStreamNonBlocking) == cudaSuccess;
        good &= cudaStreamCreateWithFlags(&s2, cudaStreamNonBlocking) == cudaSuccess;
        good &= cudaEventCreateWithFlags(&evRoot, cudaEventDisableTiming) == cudaSuccess;
        good &= cudaEventCreateWithFlags(&evA, cudaEventDisableTiming) == cudaSuccess;
        good &= cudaEventCreateWithFlags(&evB, cudaEventDisableTiming) == cudaSuccess;
        good &= cudaEventCreateWithFlags(&evE, cudaEventDisableTiming) == cudaSuccess;
        ok = good;
    }
};
static LaunchRes g_res;

// ---------------- launch ------------------------------------------------------
extern "C" void kernel_launch(void* const* d_in, const int* in_sizes, int n_in,
                              void* d_out, int out_size) {
    const float* x         = (const float*)d_in[0];
    const float* wqkv_w    = (const float*)d_in[1];
    const float* wqkv_b    = (const float*)d_in[2];
    const float* bqkv_w    = (const float*)d_in[3];
    const float* bqkv_b    = (const float*)d_in[4];
    const float* lepe_w    = (const float*)d_in[5];
    const float* lepe_b    = (const float*)d_in[6];
    const float* ca_qkv_w  = (const float*)d_in[7];
    const float* ca_qkv_b  = (const float*)d_in[8];
    const float* ca_temp   = (const float*)d_in[9];
    const float* ca_proj_w = (const float*)d_in[10];
    const float* ca_proj_b = (const float*)d_in[11];
    float* out = (float*)d_out;

    if (g_res.ok) {
        cudaEventRecord(g_res.evRoot, 0);
        cudaStreamWaitEvent(g_res.s1, g_res.evRoot, 0);
        kA_win<<<1024, 256, 66560, g_res.s1>>>(x, wqkv_w, wqkv_b);
        cudaEventRecord(g_res.evA, g_res.s1);

        kB_bra<<<1024, 256, 66560>>>(x, bqkv_w, bqkv_b);
        cudaEventRecord(g_res.evB, 0);

        cudaStreamWaitEvent(g_res.s2, g_res.evA, 0);
        cudaStreamWaitEvent(g_res.s2, g_res.evB, 0);
        kE_lepe<<<1024, 256, 57344, g_res.s2>>>(lepe_w, lepe_b);
        cudaEventRecord(g_res.evE, g_res.s2);

        kC_route<<<1024, 256>>>();
        kD_attn <<<2048, 256, 49152>>>();

        cudaStreamWaitEvent(0, g_res.evA, 0);
        cudaStreamWaitEvent(0, g_res.evE, 0);
        kF1_caqkv<<<1024, 256, 100352>>>(ca_qkv_w, ca_qkv_b);
        kF23     <<<1024, 256, 67584>>>();
        kF3b     <<<32, 256>>>(ca_temp);
        kF4_out  <<<1024, 256, 76800>>>(ca_proj_w, ca_proj_b, out);
    } else {
        kA_win   <<<1024, 256, 66560>>>(x, wqkv_w, wqkv_b);
        kB_bra   <<<1024, 256, 66560>>>(x, bqkv_w, bqkv_b);
        kC_route <<<1024, 256>>>();
        kD_attn  <<<2048, 256, 49152>>>();
        kE_lepe  <<<1024, 256, 57344>>>(lepe_w, lepe_b);
        kF1_caqkv<<<1024, 256, 100352>>>(ca_qkv_w, ca_qkv_b);
        kF23     <<<1024, 256, 67584>>>();
        kF3b     <<<32, 256>>>(ca_temp);
        kF4_out  <<<1024, 256, 76800>>>(ca_proj_w, ca_proj_b, out);
    }
}